// round 11
// baseline (speedup 1.0000x reference)
#include <cuda_runtime.h>
#include <cuda_fp16.h>
#include <math.h>
#include <stdint.h>
#include <stddef.h>

#define B_  16384
#define BP_ (B_ + 128)   // +pad rows for sparse-MoE dummies
#define D_  768
#define H_  768
#define G4_ 3072
#define KP_ 2304   // 3*768 split-K
#define E_  4
#define L_  2
#define T_  10

#define SCALE_  32.0f
#define INV32_  (1.0f / 32.0f)
#define INVSQ_  (1.0f / 1024.0f)

// GEMM tiling
#define BM 128
#define BN 256
#define BK 64
#define NSTG 3
#define A_STAGE_BYTES (BM * 128)
#define STAGE_BYTES ((BM + BN) * 128)
#define SMEM_DYN (NSTG * STAGE_BYTES)

// ---------------- scratch (static device globals; no allocation) ----------------
__device__ __align__(128) __half g_act2 [(size_t)BP_ * KP_];   // h buffer 0 / MoE activation triple
__device__ __align__(128) __half g_hb1  [(size_t)BP_ * KP_];   // h buffer 1
__device__ __align__(128) __half g_hmid2[(size_t)BP_ * KP_];
__device__ __align__(128) __half g_Wi2  [(size_t)G4_ * KP_];
__device__ __align__(128) __half g_Wh2  [(size_t)G4_ * KP_];
__device__ __align__(128) __half g_W12  [(size_t)8 * H_ * KP_];
__device__ __align__(128) __half g_W22  [(size_t)8 * D_ * KP_];
__device__ float g_xWi [(size_t)B_ * G4_];
__device__ float g_c   [(size_t)B_ * H_];
__device__ float g_hsum[(size_t)B_ * H_];
__device__ float g_x0  [(size_t)B_ * H_];
__device__ float g_accA[(size_t)BP_ * D_];
__device__ float g_accB[(size_t)BP_ * D_];
__device__ float g_hp  [B_];
__device__ float g_rem [B_];
__device__ float g_w   [BP_ * E_];          // tail rows stay 0 (dummy weight)
__device__ float g_bperm[G4_];
__device__ int   g_rowid[E_ * BP_];
__device__ int   g_cnt  [E_];
__device__ int   g_cntpad[E_];

__device__ __forceinline__ float sigf(float x) { return 1.f / (1.f + expf(-x)); }

__device__ __forceinline__ uint32_t s2u(const void* p) {
    uint32_t a;
    asm("{ .reg .u64 t; cvta.to.shared.u64 t, %1; cvt.u32.u64 %0, t; }" : "=r"(a) : "l"(p));
    return a;
}
__device__ __forceinline__ uint32_t swz(uint32_t off) { return off ^ ((off >> 3) & 0x70); }

__device__ __forceinline__ void ldsm4(uint32_t* r, uint32_t addr) {
    asm volatile("ldmatrix.sync.aligned.m8n8.x4.shared.b16 {%0,%1,%2,%3}, [%4];"
                 : "=r"(r[0]), "=r"(r[1]), "=r"(r[2]), "=r"(r[3]) : "r"(addr));
}

__device__ __forceinline__ void mma16(float* d, const uint32_t* a, uint32_t b0, uint32_t b1) {
    asm volatile(
        "mma.sync.aligned.m16n8k16.row.col.f32.f16.f16.f32 "
        "{%0,%1,%2,%3}, {%4,%5,%6,%7}, {%8,%9}, {%0,%1,%2,%3};"
        : "+f"(d[0]), "+f"(d[1]), "+f"(d[2]), "+f"(d[3])
        : "r"(a[0]), "r"(a[1]), "r"(a[2]), "r"(a[3]), "r"(b0), "r"(b1));
}

__device__ __forceinline__ void h_triple(__half* base, size_t idx, float h) {
    const float f = SCALE_ * h;
    const __half hi = __float2half_rn(f);
    const __half lo = __float2half_rn(f - __half2float(hi));
    base[idx] = hi; base[H_ + idx] = hi; base[2 * H_ + idx] = lo;
}

// LSTM quad update (fused epilogue): gate quad (i,f,g,o) for (row, j)
__device__ __forceinline__ void lstm_quad(int row, int j,
                                          float v0, float v1, float v2, float v3,
                                          const float* __restrict__ xWi,
                                          float* __restrict__ cbuf,
                                          float* __restrict__ hsumbuf,
                                          __half* __restrict__ hout)
{
    const float4 xw = *(const float4*)(xWi + (size_t)row * G4_ + 4 * j);
    const float gi = sigf(v0 + xw.x);
    const float gf = sigf(v1 + xw.y);
    const float gg = tanhf(v2 + xw.z);
    const float go = sigf(v3 + xw.w);
    const size_t o = (size_t)row * H_ + j;
    float cv = cbuf[o];
    cv = gf * cv + gi * gg;
    cbuf[o] = cv;
    const float h = go * tanhf(cv);
    hsumbuf[o] += h;
    h_triple(hout + (size_t)row * KP_, (size_t)j, h);
}

// ---------------- fp16 split-3 GEMM: C[M,N] = A'[M,Kp] @ W'[N,Kp]^T -------------
// MODE 0: C = v + bias1                                   (xWi producer)
// MODE 2: out3 = fp16-triple(relu(v + bias1)); A gathered via rowidA
// MODE 3: C[rowidC[pos]] += rowscale[rowidC[pos]*4] * (v + bias1)   (scatter acc)
// MODE 4: fused LSTM cell epilogue (addsrc=xWi interleaved; out3=h buffer)
template<int MODE>
__global__ __launch_bounds__(256, 1)
void tgemm(const __half* __restrict__ A, const __half* __restrict__ W,
           float* __restrict__ C, int N, int Kp,
           const float* __restrict__ bias1, const float* __restrict__ addsrc,
           const float* __restrict__ rowscale,
           __half* __restrict__ out3,
           const int* __restrict__ cntptr,
           const int* __restrict__ rowidA, const int* __restrict__ rowidC,
           float* __restrict__ cbuf, float* __restrict__ hsumbuf)
{
    if (cntptr && (int)(blockIdx.y * BM) >= *cntptr) return;

    extern __shared__ char smem[];
    const int tid  = threadIdx.x;
    const int lane = tid & 31;
    const int wid  = tid >> 5;
    const int m0 = blockIdx.y * BM;
    const int n0 = blockIdx.x * BN;
    const int wm = (wid >> 2) * 64;
    const int wn = (wid & 3) * 64;
    const uint32_t su = s2u(smem);

    const int NCH = Kp / BK;

    auto produce = [&](int p) {
        const uint32_t sb = su + (uint32_t)(p % NSTG) * STAGE_BYTES;
        #pragma unroll
        for (int i = 0; i < 12; ++i) {
            const int g = i * 256 + tid;
            uint32_t dst;
            const __half* src;
            if (g < 1024) {                        // A: 128 rows x 8 16B-granules
                const int row = g >> 3, c = g & 7;
                const int arow = (MODE == 2) ? rowidA[m0 + row] : (m0 + row);
                dst = sb + swz((uint32_t)(row * 128 + c * 16));
                src = A + (size_t)arow * Kp + (size_t)p * BK + c * 8;
            } else {                               // B: 256 rows x 8 granules
                const int gg = g - 1024;
                const int row = gg >> 3, c = gg & 7;
                dst = sb + A_STAGE_BYTES + swz((uint32_t)(row * 128 + c * 16));
                src = W + (size_t)(n0 + row) * Kp + (size_t)p * BK + c * 8;
            }
            asm volatile("cp.async.cg.shared.global [%0], [%1], 16;" :: "r"(dst), "l"(src));
        }
        asm volatile("cp.async.commit_group;" ::: "memory");
    };

    float acc[4][8][4];
    #pragma unroll
    for (int mt = 0; mt < 4; ++mt)
        #pragma unroll
        for (int nt = 0; nt < 8; ++nt)
            #pragma unroll
            for (int q = 0; q < 4; ++q) acc[mt][nt][q] = 0.f;

    produce(0);
    produce(1);

    const int lr = lane & 7;
    const int lg = lane >> 3;

    for (int s = 0; s < NCH; ++s) {
        asm volatile("cp.async.wait_group 1;" ::: "memory");
        __syncthreads();
        if (s + 2 < NCH) produce(s + 2);

        const uint32_t sb = su + (uint32_t)(s % NSTG) * STAGE_BYTES;

        #pragma unroll
        for (int kk = 0; kk < 4; ++kk) {
            uint32_t ar[4][4];
            #pragma unroll
            for (int mt = 0; mt < 4; ++mt) {
                const int row = wm + mt * 16 + (lg & 1) * 8 + lr;
                const int c16 = 2 * kk + (lg >> 1);
                ldsm4(ar[mt], sb + swz((uint32_t)(row * 128 + c16 * 16)));
            }
            uint32_t br[4][4];
            #pragma unroll
            for (int nt2 = 0; nt2 < 4; ++nt2) {
                const int row = wn + nt2 * 16 + (lg >> 1) * 8 + lr;
                const int c16 = 2 * kk + (lg & 1);
                ldsm4(br[nt2], sb + A_STAGE_BYTES + swz((uint32_t)(row * 128 + c16 * 16)));
            }
            #pragma unroll
            for (int mt = 0; mt < 4; ++mt)
                #pragma unroll
                for (int nt = 0; nt < 8; ++nt) {
                    const int nt2 = nt >> 1, hi = (nt & 1) * 2;
                    mma16(acc[mt][nt], ar[mt], br[nt2][hi], br[nt2][hi + 1]);
                }
        }
    }

    // ---------------- epilogue ----------------
    const int r4 = lane >> 2;
    const int c4 = lane & 3;

    if (MODE == 4) {
        #pragma unroll
        for (int mt = 0; mt < 4; ++mt) {
            #pragma unroll
            for (int nt = 0; nt < 8; ++nt) {
                const float v0 = acc[mt][nt][0] * INVSQ_;
                const float v1 = acc[mt][nt][1] * INVSQ_;
                const float v2 = acc[mt][nt][2] * INVSQ_;
                const float v3 = acc[mt][nt][3] * INVSQ_;
                const float p0 = __shfl_xor_sync(0xffffffffu, v0, 1);
                const float p1 = __shfl_xor_sync(0xffffffffu, v1, 1);
                const float p2 = __shfl_xor_sync(0xffffffffu, v2, 1);
                const float p3 = __shfl_xor_sync(0xffffffffu, v3, 1);
                if ((c4 & 1) == 0) {
                    const int j   = (n0 + wn + nt * 8 + (c4 & 2) * 2) >> 2;
                    const int row = m0 + wm + mt * 16 + r4;
                    // row: quad (i,f,g,o) = (v0,v1,p0,p1); row+8: (v2,v3,p2,p3)
                    lstm_quad(row,     j, v0, v1, p0, p1, addsrc, cbuf, hsumbuf, out3);
                    lstm_quad(row + 8, j, v2, v3, p2, p3, addsrc, cbuf, hsumbuf, out3);
                }
            }
        }
        return;
    }

    auto epi = [&](int pos, int col, float v0, float v1) {
        v0 *= INVSQ_; v1 *= INVSQ_;
        if (MODE == 0) {
            C[(size_t)pos * N + col]     = v0 + bias1[col];
            C[(size_t)pos * N + col + 1] = v1 + bias1[col + 1];
        } else if (MODE == 2) {
            const float w0 = fmaxf(v0 + bias1[col], 0.f);
            const float w1 = fmaxf(v1 + bias1[col + 1], 0.f);
            __half* o = out3 + (size_t)pos * KP_ + col;
            const float f0 = SCALE_ * w0, f1 = SCALE_ * w1;
            const __half h0 = __float2half_rn(f0), h1 = __float2half_rn(f1);
            const __half l0 = __float2half_rn(f0 - __half2float(h0));
            const __half l1 = __float2half_rn(f1 - __half2float(h1));
            o[0] = h0;           o[1] = h1;
            o[H_] = h0;          o[H_ + 1] = h1;
            o[2 * H_] = l0;      o[2 * H_ + 1] = l1;
        } else { // MODE 3
            const int crow = rowidC[pos];
            const float sc = rowscale[(size_t)crow * 4];
            const size_t off = (size_t)crow * N + col;
            C[off]     = C[off]     + sc * (v0 + bias1[col]);
            C[off + 1] = C[off + 1] + sc * (v1 + bias1[col + 1]);
        }
    };

    #pragma unroll
    for (int mt = 0; mt < 4; ++mt) {
        #pragma unroll
        for (int nt = 0; nt < 8; ++nt) {
            const int pos = m0 + wm + mt * 16 + r4;
            const int col = n0 + wn + nt * 8 + c4 * 2;
            epi(pos,     col, acc[mt][nt][0], acc[mt][nt][1]);
            epi(pos + 8, col, acc[mt][nt][2], acc[mt][nt][3]);
        }
    }
}

// ---------------- conversions ----------------
// weight layout: [hi | lo | hi]; optional gate-interleave row permutation
__global__ void convW(const float* __restrict__ src, __half* __restrict__ dst,
                      int Nr, int K, int perm4) {
    size_t i  = (size_t)blockIdx.x * blockDim.x + threadIdx.x;
    size_t n  = (size_t)Nr * K;
    size_t st = (size_t)gridDim.x * blockDim.x;
    for (; i < n; i += st) {
        int r = (int)(i / K); const int k = (int)(i % K);
        const float f = SCALE_ * src[i];
        const __half hi = __float2half_rn(f);
        const __half lo = __float2half_rn(f - __half2float(hi));
        if (perm4) r = 4 * (r % H_) + (r / H_);
        __half* o = dst + (size_t)r * (3 * K);
        o[k] = hi; o[K + k] = lo; o[2 * K + k] = hi;
    }
}
// activation layout: [hi | hi | lo]
__global__ void convA(const float* __restrict__ src, __half* __restrict__ dst,
                      int Nr, int K) {
    size_t i  = (size_t)blockIdx.x * blockDim.x + threadIdx.x;
    size_t n  = (size_t)Nr * K;
    size_t st = (size_t)gridDim.x * blockDim.x;
    for (; i < n; i += st) {
        const int r = (int)(i / K), k = (int)(i % K);
        const float f = SCALE_ * src[i];
        const __half hi = __float2half_rn(f);
        const __half lo = __float2half_rn(f - __half2float(hi));
        __half* o = dst + (size_t)r * (3 * K);
        o[k] = hi; o[K + k] = hi; o[2 * K + k] = lo;
    }
}

__global__ void perm_bias(const float* __restrict__ bi, const float* __restrict__ bh,
                          float* __restrict__ bp) {
    const int i = blockIdx.x * blockDim.x + threadIdx.x;
    if (i < G4_) {
        const int g = i & 3, j = i >> 2;
        bp[i] = bi[g * H_ + j] + bh[g * H_ + j];
    }
}

__global__ void fill0(float* p, size_t n) {
    size_t i  = (size_t)blockIdx.x * blockDim.x + threadIdx.x;
    size_t st = (size_t)gridDim.x * blockDim.x;
    for (; i < n; i += st) p[i] = 0.f;
}

// ---------------- LSTM step 0 (gates == xWi): init c,h,hsum,hp,rem ----------------
__global__ void lstm_cell0(const float* __restrict__ xWi,
                           const float* __restrict__ Whalt, const float* __restrict__ bhalt,
                           float* __restrict__ c, __half* __restrict__ hbuf,
                           float* __restrict__ hsum, float* __restrict__ hp,
                           float* __restrict__ rem)
{
    const int row = blockIdx.x;
    const int tid = threadIdx.x;   // 256
    float part = 0.f;
    #pragma unroll
    for (int it = 0; it < H_ / 256; ++it) {
        const int j = tid + it * 256;
        const float4 q = *(const float4*)(xWi + (size_t)row * G4_ + 4 * j);
        const float gi = sigf(q.x), gf = sigf(q.y), gg = tanhf(q.z), go = sigf(q.w);
        (void)gf;
        const float cv = gi * gg;                    // c0 == 0
        const float h  = go * tanhf(cv);
        const size_t o = (size_t)row * H_ + j;
        c[o] = cv;
        hsum[o] = h;
        h_triple(hbuf + (size_t)row * KP_, (size_t)j, h);
        part += h * Whalt[j];
    }
    __shared__ float red[256];
    red[tid] = part;
    __syncthreads();
    #pragma unroll
    for (int s = 128; s > 0; s >>= 1) {
        if (tid < s) red[tid] += red[tid + s];
        __syncthreads();
    }
    if (tid == 0) {
        const float y = sigf(red[0] + bhalt[0]);
        hp[row]  = y;
        rem[row] = 1.f - y;
    }
}

// ---------------- per-step halting finish (reads h triple) ----------------
__global__ void lstm_finish(const __half* __restrict__ hbuf,
                            const float* __restrict__ Whalt, const float* __restrict__ bhalt,
                            float* __restrict__ hp, float* __restrict__ rem)
{
    const int row = blockIdx.x;
    const int tid = threadIdx.x;   // 256
    const __half* hr = hbuf + (size_t)row * KP_;
    float part = 0.f;
    #pragma unroll
    for (int it = 0; it < H_ / 256; ++it) {
        const int j = tid + it * 256;
        const float h = (__half2float(hr[j]) + __half2float(hr[2 * H_ + j])) * INV32_;
        part += h * Whalt[j];
    }
    __shared__ float red[256];
    red[tid] = part;
    __syncthreads();
    #pragma unroll
    for (int s = 128; s > 0; s >>= 1) {
        if (tid < s) red[tid] += red[tid + s];
        __syncthreads();
    }
    if (tid == 0) {
        const float y = sigf(red[0] + bhalt[0]);
        float hpv = hp[row];
        hpv = hpv + y * (1.f - hpv);
        hp[row] = hpv;
        rem[row] += 1.f - hpv;
    }
}

// ---------------- avg: fp32 x0 (router) + activation triple ----------------
__global__ void avg_kernel(const float* __restrict__ hsum, const float* __restrict__ rem,
                           float* __restrict__ x0, __half* __restrict__ x02)
{
    const size_t i = (size_t)blockIdx.x * blockDim.x + threadIdx.x;
    if (i < (size_t)B_ * H_) {
        const int r = (int)(i / H_), k = (int)(i % H_);
        const float v = rem[r] * hsum[i] / 10.0f;
        x0[i] = v;
        const float f = SCALE_ * v;
        const __half hi = __float2half_rn(f);
        const __half lo = __float2half_rn(f - __half2float(hi));
        __half* o = x02 + (size_t)r * KP_;
        o[k] = hi; o[H_ + k] = hi; o[2 * H_ + k] = lo;
    }
}

// ---------------- router ----------------
__global__ void router(const float* __restrict__ x, const float* __restrict__ Wg,
                       const float* __restrict__ bg, float* __restrict__ w)
{
    const int row = blockIdx.x;
    const int tid = threadIdx.x;   // 128
    const float* xr = x + (size_t)row * H_;
    float p0 = 0.f, p1 = 0.f, p2 = 0.f, p3 = 0.f;
    for (int k = tid; k < H_; k += 128) {
        const float xv = xr[k];
        p0 += xv * Wg[k];
        p1 += xv * Wg[H_ + k];
        p2 += xv * Wg[2 * H_ + k];
        p3 += xv * Wg[3 * H_ + k];
    }
    __shared__ float red[4][128];
    red[0][tid] = p0; red[1][tid] = p1; red[2][tid] = p2; red[3][tid] = p3;
    __syncthreads();
    #pragma unroll
    for (int s = 64; s > 0; s >>= 1) {
        if (tid < s) {
            #pragma unroll
            for (int e = 0; e < 4; ++e) red[e][tid] += red[e][tid + s];
        }
        __syncthreads();
    }
    if (tid == 0) {
        float lg[4];
        #pragma unroll
        for (int e = 0; e < 4; ++e) lg[e] = red[e][0] + bg[e];
        int i1 = 0; float m1 = lg[0];
        #pragma unroll
        for (int e = 1; e < 4; ++e) if (lg[e] > m1) { m1 = lg[e]; i1 = e; }
        int i2 = -1; float m2 = -3.4e38f;
        #pragma unroll
        for (int e = 0; e < 4; ++e) if (e != i1 && lg[e] > m2) { m2 = lg[e]; i2 = e; }
        const float e2 = expf(m2 - m1);
        const float s  = 1.f + e2;
        float out4[4] = {0.f, 0.f, 0.f, 0.f};
        out4[i1] = 1.f / s;
        out4[i2] = e2 / s;
        #pragma unroll
        for (int e = 0; e < 4; ++e) w[row * 4 + e] = out4[e];
    }
}

// ---------------- sparse-MoE list building ----------------
__global__ void reset_cnt(int* cnt) {
    if (threadIdx.x < E_) cnt[threadIdx.x] = 0;
}
__global__ void build_lists(const float* __restrict__ w, int* __restrict__ cnt,
                            int* __restrict__ rowid)
{
    int r = blockIdx.x * blockDim.x + threadIdx.x;
    const int st = gridDim.x * blockDim.x;
    for (; r < B_; r += st) {
        #pragma unroll
        for (int e = 0; e < E_; ++e) {
            if (w[(size_t)r * 4 + e] > 0.f) {
                const int slot = atomicAdd(&cnt[e], 1);
                rowid[(size_t)e * BP_ + slot] = r;
            }
        }
    }
}
__global__ void pad_lists(const int* __restrict__ cnt, int* __restrict__ cntpad,
                          int* __restrict__ rowid)
{
    const int tid = threadIdx.x;   // 128
    for (int e = 0; e < E_; ++e) {
        const int n  = cnt[e];
        const int np = ((n + BM - 1) / BM) * BM;
        for (int i = n + tid; i < np; i += 128) rowid[(size_t)e * BP_ + i] = B_;
        if (tid == 0) cntpad[e] = np;
    }
}

// ---------------- final LayerNorm ----------------
__global__ void layernorm(const float* __restrict__ x, const float* __restrict__ gamma,
                          const float* __restrict__ beta, float* __restrict__ out)
{
    const int row = blockIdx.x;
    const int tid = threadIdx.x;   // 256
    const float* xr = x + (size_t)row * D_;
    float v[D_ / 256];
    float s = 0.f;
    #pragma unroll
    for (int it = 0; it < D_ / 256; ++it) { v[it] = xr[tid + it * 256]; s += v[it]; }
    __shared__ float red[256];
    red[tid] = s;
    __syncthreads();
    #pragma unroll
    for (int st = 128; st > 0; st >>= 1) {
        if (tid < st) red[tid] += red[tid + st];
        __syncthreads();
    }
    const float mu = red[0] / (float)D_;
    __syncthreads();
    float s2 = 0.f;
    #pragma unroll
    for (int it = 0; it < D_ / 256; ++it) { const float d = v[it] - mu; s2 += d * d; }
    red[tid] = s2;
    __syncthreads();
    #pragma unroll
    for (int st = 128; st > 0; st >>= 1) {
        if (tid < st) red[tid] += red[tid + st];
        __syncthreads();
    }
    const float var = red[0] / (float)D_;
    const float inv = rsqrtf(var + 1e-5f);
    #pragma unroll
    for (int it = 0; it < D_ / 256; ++it) {
        const int cc = tid + it * 256;
        out[(size_t)row * D_ + cc] = (v[it] - mu) * inv * gamma[cc] + beta[cc];
    }
}

// ---------------- host ----------------
struct Ptrs {
    __half *act2, *hb1, *hmid2, *Wi2, *Wh2, *W12, *W22;
    float *xWi, *c, *hsum, *x0, *accA, *accB, *hp, *rem, *w, *bperm;
    int *rowid, *cnt, *cntpad;
};

static Ptrs get_ptrs() {
    static Ptrs P = [] {
        Ptrs q{};
        cudaGetSymbolAddress((void**)&q.act2,   g_act2);
        cudaGetSymbolAddress((void**)&q.hb1,    g_hb1);
        cudaGetSymbolAddress((void**)&q.hmid2,  g_hmid2);
        cudaGetSymbolAddress((void**)&q.Wi2,    g_Wi2);
        cudaGetSymbolAddress((void**)&q.Wh2,    g_Wh2);
        cudaGetSymbolAddress((void**)&q.W12,    g_W12);
        cudaGetSymbolAddress((void**)&q.W22,    g_W22);
        cudaGetSymbolAddress((void**)&q.xWi,    g_xWi);
        cudaGetSymbolAddress((void**)&q.c,      g_c);
        cudaGetSymbolAddress((void**)&q.hsum,   g_hsum);
        cudaGetSymbolAddress((void**)&q.x0,     g_x0);
        cudaGetSymbolAddress((void**)&q.accA,   g_accA);
        cudaGetSymbolAddress((void**)&q.accB,   g_accB);
        cudaGetSymbolAddress((void**)&q.hp,     g_hp);
        cudaGetSymbolAddress((void**)&q.rem,    g_rem);
        cudaGetSymbolAddress((void**)&q.w,      g_w);
        cudaGetSymbolAddress((void**)&q.bperm,  g_bperm);
        cudaGetSymbolAddress((void**)&q.rowid,  g_rowid);
        cudaGetSymbolAddress((void**)&q.cnt,    g_cnt);
        cudaGetSymbolAddress((void**)&q.cntpad, g_cntpad);
        return q;
    }();
    return P;
}

extern "C" void kernel_launch(void* const* d_in, const int* in_sizes, int n_in,
                              void* d_out, int out_size)
{
    const float* x     = (const float*)d_in[0];
    const float* Wi    = (const float*)d_in[1];
    const float* Wh    = (const float*)d_in[2];
    const float* bi    = (const float*)d_in[3];
    const float* bh    = (const float*)d_in[4];
    const float* Whalt = (const float*)d_in[5];
    const float* bhalt = (const float*)d_in[6];
    const float* gateW = (const float*)d_in[7];
    const float* gateb = (const float*)d_in[8];
    const float* W1    = (const float*)d_in[9];
    const float* b1    = (const float*)d_in[10];
    const float* W2    = (const float*)d_in[11];
    const float* b2    = (const float*)d_in[12];
    const float* gamma = (const float*)d_in[13];
    const float* beta  = (const float*)d_in[14];
    float* out = (float*)d_out;

    Ptrs P = get_ptrs();

    cudaFuncSetAttribute((const void*)tgemm<0>, cudaFuncAttributeMaxDynamicSharedMemorySize, SMEM_DYN);
    cudaFuncSetAttribute((const void*)tgemm<2>, cudaFuncAttributeMaxDynamicSharedMemorySize, SMEM_DYN);
    cudaFuncSetAttribute((const void*)tgemm<3>, cudaFuncAttributeMaxDynamicSharedMemorySize, SMEM_DYN);
    cudaFuncSetAttribute((const void*)tgemm<4>, cudaFuncAttributeMaxDynamicSharedMemorySize, SMEM_DYN);

    // conversions (Wi/Wh gate-interleaved)
    convW<<<2048, 256>>>(Wi, P.Wi2, G4_, H_, 1);
    convW<<<2048, 256>>>(Wh, P.Wh2, G4_, H_, 1);
    convW<<<2048, 256>>>(W1, P.W12, 8 * H_, H_, 0);
    convW<<<2048, 256>>>(W2, P.W22, 8 * D_, H_, 0);
    convA<<<4096, 256>>>(x, P.act2, B_, D_);
    perm_bias<<<(G4_ + 255) / 256, 256>>>(bi, bh, P.bperm);

    // xWi = x @ Wi'^T + (bi+bh) permuted   [B, 3072] gate-interleaved
    dim3 gridG(G4_ / BN, B_ / BM);
    tgemm<0><<<gridG, 256, SMEM_DYN>>>(P.act2, P.Wi2, P.xWi, G4_, KP_,
                                       P.bperm, nullptr, nullptr, nullptr,
                                       nullptr, nullptr, nullptr, nullptr, nullptr);

    // t=0: gates == xWi; initializes c,hsum,hp,rem; writes h0 into act2 (hb0)
    lstm_cell0<<<B_, 256>>>(P.xWi, Whalt, bhalt, P.c, P.act2, P.hsum, P.hp, P.rem);

    // t=1..9: fused GEMM+cell, double-buffered h
    __half* hbuf[2] = { P.act2, P.hb1 };
    for (int t = 1; t < T_; ++t) {
        __half* hin  = hbuf[(t + 1) & 1];
        __half* hout = hbuf[t & 1];
        tgemm<4><<<gridG, 256, SMEM_DYN>>>(hin, P.Wh2, nullptr, G4_, KP_,
                                           nullptr, P.xWi, nullptr, hout,
                                           nullptr, nullptr, nullptr, P.c, P.hsum);
        lstm_finish<<<B_, 256>>>(hout, Whalt, bhalt, P.hp, P.rem);
    }

    // avg -> x0 (fp32 for router) + act2 triple (MoE input)
    avg_kernel<<<(B_ * H_ + 255) / 256, 256>>>(P.hsum, P.rem, P.x0, P.act2);

    // two sparse MoE levels
    dim3 gridH(H_ / BN, B_ / BM);
    const float* cur = P.x0;
    float* nxt = P.accA;
    for (int l = 0; l < L_; ++l) {
        reset_cnt<<<1, 32>>>(P.cnt);
        router<<<B_, 128>>>(cur, gateW + (size_t)l * E_ * H_, gateb + (size_t)l * E_, P.w);
        build_lists<<<64, 256>>>(P.w, P.cnt, P.rowid);
        pad_lists<<<1, 128>>>(P.cnt, P.cntpad, P.rowid);
        fill0<<<2048, 256>>>(nxt, (size_t)BP_ * D_);
        for (int e = 0; e < E_; ++e) {
            const size_t le = (size_t)l * E_ + e;
            tgemm<2><<<gridH, 256, SMEM_DYN>>>(P.act2, P.W12 + le * H_ * KP_, nullptr, H_, KP_,
                                               b1 + le * H_, nullptr, nullptr, P.hmid2,
                                               P.cntpad + e, P.rowid + (size_t)e * BP_,
                                               nullptr, nullptr, nullptr);
            tgemm<3><<<gridH, 256, SMEM_DYN>>>(P.hmid2, P.W22 + le * (size_t)D_ * KP_, nxt, D_, KP_,
                                               b2 + le * D_, nullptr, P.w + e, nullptr,
                                               P.cntpad + e, nullptr,
                                               P.rowid + (size_t)e * BP_, nullptr, nullptr);
        }
        if (l + 1 < L_) convA<<<4096, 256>>>(nxt, P.act2, B_, D_);
        cur = nxt;
        nxt = P.accB;
    }

    layernorm<<<B_, 256>>>(cur, gamma, beta, out);
}

// round 15
// speedup vs baseline: 1.4764x; 1.4764x over previous
#include <cuda_runtime.h>
#include <cuda_fp16.h>
#include <math.h>
#include <stdint.h>
#include <stddef.h>

#define B_  16384
#define BP_ (B_ + 128)   // +pad rows for sparse-MoE dummies
#define D_  768
#define H_  768
#define G4_ 3072
#define KP_ 2304   // 3*768 split-K
#define E_  4
#define L_  2
#define T_  10

#define SCALE_  32.0f
#define INVSQ_  (1.0f / 1024.0f)

// GEMM tiling
#define BM 128
#define BN 256
#define BK 64
#define NSTG 3
#define A_STAGE_BYTES (BM * 128)
#define STAGE_BYTES ((BM + BN) * 128)
#define SMEM_DYN (NSTG * STAGE_BYTES)

// ---------------- scratch (static device globals; no allocation) ----------------
__device__ __align__(128) __half g_act2 [(size_t)BP_ * KP_];  // pad rows stay zero
__device__ __align__(128) __half g_hmid2[(size_t)BP_ * KP_];
__device__ __align__(128) __half g_Wi2  [(size_t)G4_ * KP_];
__device__ __align__(128) __half g_Wh2  [(size_t)G4_ * KP_];
__device__ __align__(128) __half g_W12  [(size_t)8 * H_ * KP_];
__device__ __align__(128) __half g_W22  [(size_t)8 * D_ * KP_];
__device__ float g_xWi [(size_t)B_ * G4_];
__device__ float g_gates[(size_t)B_ * G4_];
__device__ float g_c   [(size_t)B_ * H_];
__device__ float g_hsum[(size_t)B_ * H_];
__device__ float g_x0  [(size_t)B_ * H_];
__device__ float g_accA[(size_t)BP_ * D_];
__device__ float g_accB[(size_t)BP_ * D_];
__device__ float g_hp  [B_];
__device__ float g_rem [B_];
__device__ float g_w   [BP_ * E_];          // pad rows stay 0 (dummy weight)
__device__ int   g_rowid[E_ * BP_];
__device__ int   g_cnt  [E_];
__device__ int   g_cntpad[E_];

__device__ __forceinline__ float sigf(float x) { return 1.f / (1.f + expf(-x)); }

__device__ __forceinline__ uint32_t s2u(const void* p) {
    uint32_t a;
    asm("{ .reg .u64 t; cvta.to.shared.u64 t, %1; cvt.u32.u64 %0, t; }" : "=r"(a) : "l"(p));
    return a;
}
__device__ __forceinline__ uint32_t swz(uint32_t off) { return off ^ ((off >> 3) & 0x70); }

__device__ __forceinline__ void ldsm4(uint32_t* r, uint32_t addr) {
    asm volatile("ldmatrix.sync.aligned.m8n8.x4.shared.b16 {%0,%1,%2,%3}, [%4];"
                 : "=r"(r[0]), "=r"(r[1]), "=r"(r[2]), "=r"(r[3]) : "r"(addr));
}

__device__ __forceinline__ void mma16(float* d, const uint32_t* a, uint32_t b0, uint32_t b1) {
    asm volatile(
        "mma.sync.aligned.m16n8k16.row.col.f32.f16.f16.f32 "
        "{%0,%1,%2,%3}, {%4,%5,%6,%7}, {%8,%9}, {%0,%1,%2,%3};"
        : "+f"(d[0]), "+f"(d[1]), "+f"(d[2]), "+f"(d[3])
        : "r"(a[0]), "r"(a[1]), "r"(a[2]), "r"(a[3]), "r"(b0), "r"(b1));
}

// ---------------- fp16 split-3 GEMM: C[M,N] = A'[M,Kp] @ W'[N,Kp]^T -------------
// Operands pre-scaled by 32; accumulator scaled by 1024; epilogue applies INVSQ_.
// MODE 0: C = v + bias1 + bias2                       (xWi producer)
// MODE 1: C = v + addsrc                              (recurrent gates)
// MODE 2: out3 = fp16-triple(relu(v + bias1)); A rows gathered via rowidA
// MODE 3: C[rowidC[pos]] += rowscale[rowidC[pos]*rs_stride] * (v + bias1)
template<int MODE>
__global__ __launch_bounds__(256, 1)
void tgemm(const __half* __restrict__ A, const __half* __restrict__ W,
           float* __restrict__ C, int N, int Kp,
           const float* __restrict__ bias1, const float* __restrict__ bias2,
           const float* __restrict__ addsrc,
           const float* __restrict__ rowscale, int rs_stride,
           __half* __restrict__ out3,
           const int* __restrict__ cntptr,
           const int* __restrict__ rowidA, const int* __restrict__ rowidC)
{
    if ((MODE == 2 || MODE == 3) && (int)(blockIdx.y * BM) >= *cntptr) return;

    extern __shared__ char smem[];
    const int tid  = threadIdx.x;
    const int lane = tid & 31;
    const int wid  = tid >> 5;
    const int m0 = blockIdx.y * BM;
    const int n0 = blockIdx.x * BN;
    const int wm = (wid >> 2) * 64;
    const int wn = (wid & 3) * 64;
    const uint32_t su = s2u(smem);

    const int NCH = Kp / BK;

    auto produce = [&](int p) {
        const uint32_t sb = su + (uint32_t)(p % NSTG) * STAGE_BYTES;
        #pragma unroll
        for (int i = 0; i < 12; ++i) {
            const int g = i * 256 + tid;
            uint32_t dst;
            const __half* src;
            if (g < 1024) {                        // A: 128 rows x 8 16B-granules
                const int row = g >> 3, c = g & 7;
                const int arow = (MODE == 2) ? rowidA[m0 + row] : (m0 + row);
                dst = sb + swz((uint32_t)(row * 128 + c * 16));
                src = A + (size_t)arow * Kp + (size_t)p * BK + c * 8;
            } else {                               // B: 256 rows x 8 granules
                const int gg = g - 1024;
                const int row = gg >> 3, c = gg & 7;
                dst = sb + A_STAGE_BYTES + swz((uint32_t)(row * 128 + c * 16));
                src = W + (size_t)(n0 + row) * Kp + (size_t)p * BK + c * 8;
            }
            asm volatile("cp.async.cg.shared.global [%0], [%1], 16;" :: "r"(dst), "l"(src));
        }
        asm volatile("cp.async.commit_group;" ::: "memory");
    };

    float acc[4][8][4];
    #pragma unroll
    for (int mt = 0; mt < 4; ++mt)
        #pragma unroll
        for (int nt = 0; nt < 8; ++nt)
            #pragma unroll
            for (int q = 0; q < 4; ++q) acc[mt][nt][q] = 0.f;

    produce(0);
    produce(1);

    const int lr = lane & 7;
    const int lg = lane >> 3;

    for (int s = 0; s < NCH; ++s) {
        asm volatile("cp.async.wait_group 1;" ::: "memory");
        __syncthreads();
        if (s + 2 < NCH) produce(s + 2);

        const uint32_t sb = su + (uint32_t)(s % NSTG) * STAGE_BYTES;

        #pragma unroll
        for (int kk = 0; kk < 4; ++kk) {
            uint32_t ar[4][4];
            #pragma unroll
            for (int mt = 0; mt < 4; ++mt) {
                const int row = wm + mt * 16 + (lg & 1) * 8 + lr;
                const int c16 = 2 * kk + (lg >> 1);
                ldsm4(ar[mt], sb + swz((uint32_t)(row * 128 + c16 * 16)));
            }
            uint32_t br[4][4];
            #pragma unroll
            for (int nt2 = 0; nt2 < 4; ++nt2) {
                const int row = wn + nt2 * 16 + (lg >> 1) * 8 + lr;
                const int c16 = 2 * kk + (lg & 1);
                ldsm4(br[nt2], sb + A_STAGE_BYTES + swz((uint32_t)(row * 128 + c16 * 16)));
            }
            #pragma unroll
            for (int mt = 0; mt < 4; ++mt)
                #pragma unroll
                for (int nt = 0; nt < 8; ++nt) {
                    const int nt2 = nt >> 1, hi = (nt & 1) * 2;
                    mma16(acc[mt][nt], ar[mt], br[nt2][hi], br[nt2][hi + 1]);
                }
        }
    }

    // ---------------- epilogue ----------------
    const int r4 = lane >> 2;
    const int c4 = lane & 3;

    auto epi = [&](int pos, int col, float v0, float v1) {
        v0 *= INVSQ_; v1 *= INVSQ_;
        if (MODE == 0) {
            C[(size_t)pos * N + col]     = v0 + bias1[col]     + bias2[col];
            C[(size_t)pos * N + col + 1] = v1 + bias1[col + 1] + bias2[col + 1];
        } else if (MODE == 1) {
            const size_t off = (size_t)pos * N + col;
            C[off]     = v0 + addsrc[off];
            C[off + 1] = v1 + addsrc[off + 1];
        } else if (MODE == 2) {
            const float w0 = fmaxf(v0 + bias1[col], 0.f);
            const float w1 = fmaxf(v1 + bias1[col + 1], 0.f);
            __half* o = out3 + (size_t)pos * KP_ + col;
            const float f0 = SCALE_ * w0, f1 = SCALE_ * w1;
            const __half h0 = __float2half_rn(f0), h1 = __float2half_rn(f1);
            const __half l0 = __float2half_rn(f0 - __half2float(h0));
            const __half l1 = __float2half_rn(f1 - __half2float(h1));
            o[0] = h0;           o[1] = h1;
            o[H_] = h0;          o[H_ + 1] = h1;
            o[2 * H_] = l0;      o[2 * H_ + 1] = l1;
        } else { // MODE 3
            const int crow = rowidC[pos];
            const float sc = rowscale[(size_t)crow * rs_stride];
            const size_t off = (size_t)crow * N + col;
            C[off]     = C[off]     + sc * (v0 + bias1[col]);
            C[off + 1] = C[off + 1] + sc * (v1 + bias1[col + 1]);
        }
    };

    #pragma unroll
    for (int mt = 0; mt < 4; ++mt) {
        #pragma unroll
        for (int nt = 0; nt < 8; ++nt) {
            const int pos = m0 + wm + mt * 16 + r4;
            const int col = n0 + wn + nt * 8 + c4 * 2;
            epi(pos,     col, acc[mt][nt][0], acc[mt][nt][1]);
            epi(pos + 8, col, acc[mt][nt][2], acc[mt][nt][3]);
        }
    }
}

// ---------------- conversion kernels ----------------
// weight layout: [hi | lo | hi]
__global__ void convW(const float* __restrict__ src, __half* __restrict__ dst,
                      int Nr, int K) {
    size_t i  = (size_t)blockIdx.x * blockDim.x + threadIdx.x;
    size_t n  = (size_t)Nr * K;
    size_t st = (size_t)gridDim.x * blockDim.x;
    for (; i < n; i += st) {
        const int r = (int)(i / K), k = (int)(i % K);
        const float f = SCALE_ * src[i];
        const __half hi = __float2half_rn(f);
        const __half lo = __float2half_rn(f - __half2float(hi));
        __half* o = dst + (size_t)r * (3 * K);
        o[k] = hi; o[K + k] = lo; o[2 * K + k] = hi;
    }
}
// activation layout: [hi | hi | lo]
__global__ void convA(const float* __restrict__ src, __half* __restrict__ dst,
                      int Nr, int K) {
    size_t i  = (size_t)blockIdx.x * blockDim.x + threadIdx.x;
    size_t n  = (size_t)Nr * K;
    size_t st = (size_t)gridDim.x * blockDim.x;
    for (; i < n; i += st) {
        const int r = (int)(i / K), k = (int)(i % K);
        const float f = SCALE_ * src[i];
        const __half hi = __float2half_rn(f);
        const __half lo = __float2half_rn(f - __half2float(hi));
        __half* o = dst + (size_t)r * (3 * K);
        o[k] = hi; o[K + k] = hi; o[2 * K + k] = lo;
    }
}

__global__ void fill0(float* p, size_t n) {
    size_t i  = (size_t)blockIdx.x * blockDim.x + threadIdx.x;
    size_t st = (size_t)gridDim.x * blockDim.x;
    for (; i < n; i += st) p[i] = 0.f;
}

// ---------------- fused LSTM cell: writes h as x32 fp16 split triple ------------
__global__ void lstm_cell(const float* __restrict__ gates,
                          const float* __restrict__ Whalt, const float* __restrict__ bhalt,
                          float* __restrict__ c, __half* __restrict__ h2,
                          float* __restrict__ hsum, float* __restrict__ hp,
                          float* __restrict__ rem)
{
    const int row = blockIdx.x;
    const int tid = threadIdx.x;   // 256
    const float* gr = gates + (size_t)row * G4_;
    __half* hr = h2 + (size_t)row * KP_;
    float part = 0.f;
    #pragma unroll
    for (int it = 0; it < H_ / 256; ++it) {
        const int idx = tid + it * 256;
        const float gi = gr[idx];
        const float gf = gr[H_ + idx];
        const float gg = gr[2 * H_ + idx];
        const float go = gr[3 * H_ + idx];
        const size_t o = (size_t)row * H_ + idx;
        float cv = c[o];
        cv = sigf(gf) * cv + sigf(gi) * tanhf(gg);
        const float hv = sigf(go) * tanhf(cv);
        c[o] = cv;
        const float f = SCALE_ * hv;
        const __half hi = __float2half_rn(f);
        const __half lo = __float2half_rn(f - __half2float(hi));
        hr[idx] = hi; hr[H_ + idx] = hi; hr[2 * H_ + idx] = lo;
        hsum[o] += hv;
        part += hv * Whalt[idx];
    }
    __shared__ float red[256];
    red[tid] = part;
    __syncthreads();
    #pragma unroll
    for (int s = 128; s > 0; s >>= 1) {
        if (tid < s) red[tid] += red[tid + s];
        __syncthreads();
    }
    if (tid == 0) {
        const float y = sigf(red[0] + bhalt[0]);
        float hpv = hp[row];
        hpv = hpv + y * (1.f - hpv);
        hp[row] = hpv;
        rem[row] += 1.f - hpv;
    }
}

// ---------------- avg: fp32 x0 (for router) + fp16 triple ----------------
__global__ void avg_kernel(const float* __restrict__ hsum, const float* __restrict__ rem,
                           float* __restrict__ x0, __half* __restrict__ x02)
{
    const size_t i = (size_t)blockIdx.x * blockDim.x + threadIdx.x;
    if (i < (size_t)B_ * H_) {
        const int r = (int)(i / H_), k = (int)(i % H_);
        const float v = rem[r] * hsum[i] / 10.0f;
        x0[i] = v;
        const float f = SCALE_ * v;
        const __half hi = __float2half_rn(f);
        const __half lo = __float2half_rn(f - __half2float(hi));
        __half* o = x02 + (size_t)r * KP_;
        o[k] = hi; o[H_ + k] = hi; o[2 * H_ + k] = lo;
    }
}

// ---------------- router: fp32 logits -> top2 softmax weights ----------------
__global__ void router(const float* __restrict__ x, const float* __restrict__ Wg,
                       const float* __restrict__ bg, float* __restrict__ w)
{
    const int row = blockIdx.x;
    const int tid = threadIdx.x;   // 128
    const float* xr = x + (size_t)row * H_;
    float p0 = 0.f, p1 = 0.f, p2 = 0.f, p3 = 0.f;
    for (int k = tid; k < H_; k += 128) {
        const float xv = xr[k];
        p0 += xv * Wg[k];
        p1 += xv * Wg[H_ + k];
        p2 += xv * Wg[2 * H_ + k];
        p3 += xv * Wg[3 * H_ + k];
    }
    __shared__ float red[4][128];
    red[0][tid] = p0; red[1][tid] = p1; red[2][tid] = p2; red[3][tid] = p3;
    __syncthreads();
    #pragma unroll
    for (int s = 64; s > 0; s >>= 1) {
        if (tid < s) {
            #pragma unroll
            for (int e = 0; e < 4; ++e) red[e][tid] += red[e][tid + s];
        }
        __syncthreads();
    }
    if (tid == 0) {
        float lg[4];
        #pragma unroll
        for (int e = 0; e < 4; ++e) lg[e] = red[e][0] + bg[e];
        int i1 = 0; float m1 = lg[0];
        #pragma unroll
        for (int e = 1; e < 4; ++e) if (lg[e] > m1) { m1 = lg[e]; i1 = e; }
        int i2 = -1; float m2 = -3.4e38f;
        #pragma unroll
        for (int e = 0; e < 4; ++e) if (e != i1 && lg[e] > m2) { m2 = lg[e]; i2 = e; }
        const float e2 = expf(m2 - m1);
        const float s  = 1.f + e2;
        float out4[4] = {0.f, 0.f, 0.f, 0.f};
        out4[i1] = 1.f / s;
        out4[i2] = e2 / s;
        #pragma unroll
        for (int e = 0; e < 4; ++e) w[row * 4 + e] = out4[e];
    }
}

// ---------------- sparse-MoE list building ----------------
__global__ void reset_cnt(int* cnt) {
    if (threadIdx.x < E_) cnt[threadIdx.x] = 0;
}
__global__ void build_lists(const float* __restrict__ w, int* __restrict__ cnt,
                            int* __restrict__ rowid)
{
    int r = blockIdx.x * blockDim.x + threadIdx.x;
    const int st = gridDim.x * blockDim.x;
    for (; r < B_; r += st) {
        #pragma unroll
        for (int e = 0; e < E_; ++e) {
            if (w[(size_t)r * 4 + e] > 0.f) {
                const int slot = atomicAdd(&cnt[e], 1);
                rowid[(size_t)e * BP_ + slot] = r;
            }
        }
    }
}
__global__ void pad_lists(const int* __restrict__ cnt, int* __restrict__ cntpad,
                          int* __restrict__ rowid)
{
    const int tid = threadIdx.x;   // 128
    for (int e = 0; e < E_; ++e) {
        const int n  = cnt[e];
        const int np = ((n + BM - 1) / BM) * BM;
        for (int i = n + tid; i < np; i += 128) rowid[(size_t)e * BP_ + i] = B_;
        if (tid == 0) cntpad[e] = np;
    }
}

// ---------------- final LayerNorm ----------------
__global__ void layernorm(const float* __restrict__ x, const float* __restrict__ gamma,
                          const float* __restrict__ beta, float* __restrict__ out)
{
    const int row = blockIdx.x;
    const int tid = threadIdx.x;   // 256
    const float* xr = x + (size_t)row * D_;
    float v[D_ / 256];
    float s = 0.f;
    #pragma unroll
    for (int it = 0; it < D_ / 256; ++it) { v[it] = xr[tid + it * 256]; s += v[it]; }
    __shared__ float red[256];
    red[tid] = s;
    __syncthreads();
    #pragma unroll
    for (int st = 128; st > 0; st >>= 1) {
        if (tid < st) red[tid] += red[tid + st];
        __syncthreads();
    }
    const float mu = red[0] / (float)D_;
    __syncthreads();
    float s2 = 0.f;
    #pragma unroll
    for (int it = 0; it < D_ / 256; ++it) { const float d = v[it] - mu; s2 += d * d; }
    red[tid] = s2;
    __syncthreads();
    #pragma unroll
    for (int st = 128; st > 0; st >>= 1) {
        if (tid < st) red[tid] += red[tid + st];
        __syncthreads();
    }
    const float var = red[0] / (float)D_;
    const float inv = rsqrtf(var + 1e-5f);
    #pragma unroll
    for (int it = 0; it < D_ / 256; ++it) {
        const int cc = tid + it * 256;
        out[(size_t)row * D_ + cc] = (v[it] - mu) * inv * gamma[cc] + beta[cc];
    }
}

// ---------------- host ----------------
struct Ptrs {
    __half *act2, *hmid2, *Wi2, *Wh2, *W12, *W22;
    float *xWi, *gates, *c, *hsum, *x0, *accA, *accB, *hp, *rem, *w;
    int *rowid, *cnt, *cntpad;
};

static Ptrs get_ptrs() {
    static Ptrs P = [] {
        Ptrs q{};
        cudaGetSymbolAddress((void**)&q.act2,   g_act2);
        cudaGetSymbolAddress((void**)&q.hmid2,  g_hmid2);
        cudaGetSymbolAddress((void**)&q.Wi2,    g_Wi2);
        cudaGetSymbolAddress((void**)&q.Wh2,    g_Wh2);
        cudaGetSymbolAddress((void**)&q.W12,    g_W12);
        cudaGetSymbolAddress((void**)&q.W22,    g_W22);
        cudaGetSymbolAddress((void**)&q.xWi,    g_xWi);
        cudaGetSymbolAddress((void**)&q.gates,  g_gates);
        cudaGetSymbolAddress((void**)&q.c,      g_c);
        cudaGetSymbolAddress((void**)&q.hsum,   g_hsum);
        cudaGetSymbolAddress((void**)&q.x0,     g_x0);
        cudaGetSymbolAddress((void**)&q.accA,   g_accA);
        cudaGetSymbolAddress((void**)&q.accB,   g_accB);
        cudaGetSymbolAddress((void**)&q.hp,     g_hp);
        cudaGetSymbolAddress((void**)&q.rem,    g_rem);
        cudaGetSymbolAddress((void**)&q.w,      g_w);
        cudaGetSymbolAddress((void**)&q.rowid,  g_rowid);
        cudaGetSymbolAddress((void**)&q.cnt,    g_cnt);
        cudaGetSymbolAddress((void**)&q.cntpad, g_cntpad);
        return q;
    }();
    return P;
}

extern "C" void kernel_launch(void* const* d_in, const int* in_sizes, int n_in,
                              void* d_out, int out_size)
{
    const float* x     = (const float*)d_in[0];
    const float* Wi    = (const float*)d_in[1];
    const float* Wh    = (const float*)d_in[2];
    const float* bi    = (const float*)d_in[3];
    const float* bh    = (const float*)d_in[4];
    const float* Whalt = (const float*)d_in[5];
    const float* bhalt = (const float*)d_in[6];
    const float* gateW = (const float*)d_in[7];
    const float* gateb = (const float*)d_in[8];
    const float* W1    = (const float*)d_in[9];
    const float* b1    = (const float*)d_in[10];
    const float* W2    = (const float*)d_in[11];
    const float* b2    = (const float*)d_in[12];
    const float* gamma = (const float*)d_in[13];
    const float* beta  = (const float*)d_in[14];
    float* out = (float*)d_out;

    Ptrs P = get_ptrs();

    cudaFuncSetAttribute((const void*)tgemm<0>, cudaFuncAttributeMaxDynamicSharedMemorySize, SMEM_DYN);
    cudaFuncSetAttribute((const void*)tgemm<1>, cudaFuncAttributeMaxDynamicSharedMemorySize, SMEM_DYN);
    cudaFuncSetAttribute((const void*)tgemm<2>, cudaFuncAttributeMaxDynamicSharedMemorySize, SMEM_DYN);
    cudaFuncSetAttribute((const void*)tgemm<3>, cudaFuncAttributeMaxDynamicSharedMemorySize, SMEM_DYN);

    // weight + input conversion to x32 fp16 split triples
    convW<<<2048, 256>>>(Wi, P.Wi2, G4_, H_);
    convW<<<2048, 256>>>(Wh, P.Wh2, G4_, H_);
    convW<<<2048, 256>>>(W1, P.W12, 8 * H_, H_);
    convW<<<2048, 256>>>(W2, P.W22, 8 * D_, H_);
    convA<<<4096, 256>>>(x, P.act2, B_, D_);

    // zero recurrent state
    fill0<<<2048, 256>>>(P.c,    (size_t)B_ * H_);
    fill0<<<2048, 256>>>(P.hsum, (size_t)B_ * H_);
    fill0<<<64,   256>>>(P.hp,   (size_t)B_);
    fill0<<<64,   256>>>(P.rem,  (size_t)B_);

    // xWi = x @ Wi^T + bi + bh
    dim3 gridG(G4_ / BN, B_ / BM);
    tgemm<0><<<gridG, 256, SMEM_DYN>>>(P.act2, P.Wi2, P.xWi, G4_, KP_,
                                       bi, bh, nullptr, nullptr, 0, nullptr,
                                       nullptr, nullptr, nullptr);

    for (int t = 0; t < T_; ++t) {
        const float* gptr;
        if (t == 0) {
            gptr = P.xWi;   // h==0 -> gates == xWi
        } else {
            tgemm<1><<<gridG, 256, SMEM_DYN>>>(P.act2, P.Wh2, P.gates, G4_, KP_,
                                               nullptr, nullptr, P.xWi, nullptr, 0, nullptr,
                                               nullptr, nullptr, nullptr);
            gptr = P.gates;
        }
        lstm_cell<<<B_, 256>>>(gptr, Whalt, bhalt, P.c, P.act2, P.hsum, P.hp, P.rem);
    }

    avg_kernel<<<(B_ * H_ + 255) / 256, 256>>>(P.hsum, P.rem, P.x0, P.act2);

    // two sparse MoE levels (bitwise-identical math to dense: omitted terms had weight 0)
    dim3 gridH(H_ / BN, B_ / BM);
    const float* cur = P.x0;
    float* nxt = P.accA;
    for (int l = 0; l < L_; ++l) {
        reset_cnt<<<1, 32>>>(P.cnt);
        router<<<B_, 128>>>(cur, gateW + (size_t)l * E_ * H_, gateb + (size_t)l * E_, P.w);
        build_lists<<<64, 256>>>(P.w, P.cnt, P.rowid);
        pad_lists<<<1, 128>>>(P.cnt, P.cntpad, P.rowid);
        fill0<<<2048, 256>>>(nxt, (size_t)BP_ * D_);
        for (int e = 0; e < E_; ++e) {
            const size_t le = (size_t)l * E_ + e;
            tgemm<2><<<gridH, 256, SMEM_DYN>>>(P.act2, P.W12 + le * H_ * KP_, nullptr, H_, KP_,
                                               b1 + le * H_, nullptr, nullptr, nullptr, 0,
                                               P.hmid2,
                                               P.cntpad + e, P.rowid + (size_t)e * BP_, nullptr);
            tgemm<3><<<gridH, 256, SMEM_DYN>>>(P.hmid2, P.W22 + le * (size_t)D_ * KP_, nxt, D_, KP_,
                                               b2 + le * D_, nullptr, nullptr, P.w + e, E_,
                                               nullptr,
                                               P.cntpad + e, nullptr, P.rowid + (size_t)e * BP_);
        }
        if (l + 1 < L_) convA<<<4096, 256>>>(nxt, P.act2, B_, D_);
        cur = nxt;
        nxt = P.accB;
    }

    layernorm<<<B_, 256>>>(cur, gamma, beta, out);
}

// round 16
// speedup vs baseline: 1.5665x; 1.0611x over previous
#include <cuda_runtime.h>
#include <cuda_fp16.h>
#include <math.h>
#include <stdint.h>
#include <stddef.h>

#define B_   16384
#define BP_  (B_ + 128)
#define D_   768
#define H_   768
#define G4_  3072
#define KP_  2304   // split-3 K
#define KP2_ 1536   // split-2 K
#define E_   4
#define T_   10

#define SCALE_  32.0f
#define INVSQ_  (1.0f / 1024.0f)

// GEMM tiling
#define BM 128
#define BN 256
#define BK 64
#define NSTG 3
#define A_STAGE_BYTES (BM * 128)
#define STAGE_BYTES ((BM + BN) * 128)
#define SMEM_DYN (NSTG * STAGE_BYTES)

// ---------------- scratch (static device globals; no allocation) ----------------
__device__ __align__(128) __half g_act2 [(size_t)BP_ * KP_];  // lvl1 triple / lvl2 packed pair
__device__ __align__(128) __half g_hmid2[(size_t)BP_ * KP_];
__device__ __align__(128) __half g_Wi2  [(size_t)G4_ * KP_];
__device__ __align__(128) __half g_Wh2  [(size_t)G4_ * KP_];
__device__ __align__(128) __half g_W12  [(size_t)4 * H_ * KP_];   // level-1 triple
__device__ __align__(128) __half g_W22  [(size_t)4 * D_ * KP_];
__device__ __align__(128) __half g_W12b [(size_t)4 * H_ * KP2_];  // level-2 pair
__device__ __align__(128) __half g_W22b [(size_t)4 * D_ * KP2_];
__device__ __align__(128) float g_xWi [(size_t)B_ * G4_];
__device__ __align__(128) float g_gates[(size_t)B_ * G4_];        // also lvl2 hmid pair (half view)
__device__ __align__(128) float g_c   [(size_t)B_ * H_];
__device__ __align__(128) float g_hsum[(size_t)B_ * H_];
__device__ __align__(128) float g_x0  [(size_t)B_ * H_];
__device__ __align__(128) float g_accA[(size_t)BP_ * D_];
__device__ __align__(128) float g_accB[(size_t)BP_ * D_];
__device__ float g_hp  [B_];
__device__ float g_rem [B_];
__device__ float g_w   [BP_ * E_];          // pad rows stay 0
__device__ int   g_rowid[E_ * BP_];
__device__ int   g_cnt  [E_];
__device__ int   g_cntpad[E_];

// fast transcendental helpers (rel err ~1e-6; negligible vs error budget)
__device__ __forceinline__ float sigf(float x) {
    return __fdividef(1.f, 1.f + __expf(-x));
}
__device__ __forceinline__ float tanhf_fast(float x) {
    const float e = __expf(-2.f * fabsf(x));
    return copysignf(__fdividef(1.f - e, 1.f + e), x);
}

__device__ __forceinline__ uint32_t s2u(const void* p) {
    uint32_t a;
    asm("{ .reg .u64 t; cvta.to.shared.u64 t, %1; cvt.u32.u64 %0, t; }" : "=r"(a) : "l"(p));
    return a;
}
__device__ __forceinline__ uint32_t swz(uint32_t off) { return off ^ ((off >> 3) & 0x70); }

__device__ __forceinline__ void ldsm4(uint32_t* r, uint32_t addr) {
    asm volatile("ldmatrix.sync.aligned.m8n8.x4.shared.b16 {%0,%1,%2,%3}, [%4];"
                 : "=r"(r[0]), "=r"(r[1]), "=r"(r[2]), "=r"(r[3]) : "r"(addr));
}

__device__ __forceinline__ void mma16(float* d, const uint32_t* a, uint32_t b0, uint32_t b1) {
    asm volatile(
        "mma.sync.aligned.m16n8k16.row.col.f32.f16.f16.f32 "
        "{%0,%1,%2,%3}, {%4,%5,%6,%7}, {%8,%9}, {%0,%1,%2,%3};"
        : "+f"(d[0]), "+f"(d[1]), "+f"(d[2]), "+f"(d[3])
        : "r"(a[0]), "r"(a[1]), "r"(a[2]), "r"(a[3]), "r"(b0), "r"(b1));
}

// ---------------- fp16 split GEMM: C[M,N] = A'[M,Kp] @ W'[N,Kp]^T ----------------
// MODE 0: C = v + bias1 + bias2                       (xWi producer)
// MODE 1: C = v + addsrc                              (recurrent gates)
// MODE 2: hmid triple [hi|hi|lo] = relu(v + bias1); A gathered (lvl-1)
// MODE 3: C[rowidC[pos]] += rowscale[rowidC[pos]*rs_stride] * (v + bias1)
// MODE 5: hmid pair   [hi|lo]    = relu(v + bias1); A gathered (lvl-2)
template<int MODE>
__global__ __launch_bounds__(256, 1)
void tgemm(const __half* __restrict__ A, const __half* __restrict__ W,
           float* __restrict__ C, int N, int Kp,
           const float* __restrict__ bias1, const float* __restrict__ bias2,
           const float* __restrict__ addsrc,
           const float* __restrict__ rowscale, int rs_stride,
           __half* __restrict__ out3,
           const int* __restrict__ cntptr,
           const int* __restrict__ rowidA, const int* __restrict__ rowidC)
{
    if ((MODE == 2 || MODE == 3 || MODE == 5) && (int)(blockIdx.y * BM) >= *cntptr) return;

    extern __shared__ char smem[];
    const int tid  = threadIdx.x;
    const int lane = tid & 31;
    const int wid  = tid >> 5;
    const int m0 = blockIdx.y * BM;
    const int n0 = blockIdx.x * BN;
    const int wm = (wid >> 2) * 64;
    const int wn = (wid & 3) * 64;
    const uint32_t su = s2u(smem);

    const int NCH = Kp / BK;

    auto produce = [&](int p) {
        const uint32_t sb = su + (uint32_t)(p % NSTG) * STAGE_BYTES;
        #pragma unroll
        for (int i = 0; i < 12; ++i) {
            const int g = i * 256 + tid;
            uint32_t dst;
            const __half* src;
            if (g < 1024) {
                const int row = g >> 3, c = g & 7;
                const int arow = (MODE == 2 || MODE == 5) ? rowidA[m0 + row] : (m0 + row);
                dst = sb + swz((uint32_t)(row * 128 + c * 16));
                src = A + (size_t)arow * Kp + (size_t)p * BK + c * 8;
            } else {
                const int gg = g - 1024;
                const int row = gg >> 3, c = gg & 7;
                dst = sb + A_STAGE_BYTES + swz((uint32_t)(row * 128 + c * 16));
                src = W + (size_t)(n0 + row) * Kp + (size_t)p * BK + c * 8;
            }
            asm volatile("cp.async.cg.shared.global [%0], [%1], 16;" :: "r"(dst), "l"(src));
        }
        asm volatile("cp.async.commit_group;" ::: "memory");
    };

    float acc[4][8][4];
    #pragma unroll
    for (int mt = 0; mt < 4; ++mt)
        #pragma unroll
        for (int nt = 0; nt < 8; ++nt)
            #pragma unroll
            for (int q = 0; q < 4; ++q) acc[mt][nt][q] = 0.f;

    produce(0);
    produce(1);

    const int lr = lane & 7;
    const int lg = lane >> 3;

    for (int s = 0; s < NCH; ++s) {
        asm volatile("cp.async.wait_group 1;" ::: "memory");
        __syncthreads();
        if (s + 2 < NCH) produce(s + 2);

        const uint32_t sb = su + (uint32_t)(s % NSTG) * STAGE_BYTES;

        #pragma unroll
        for (int kk = 0; kk < 4; ++kk) {
            uint32_t ar[4][4];
            #pragma unroll
            for (int mt = 0; mt < 4; ++mt) {
                const int row = wm + mt * 16 + (lg & 1) * 8 + lr;
                const int c16 = 2 * kk + (lg >> 1);
                ldsm4(ar[mt], sb + swz((uint32_t)(row * 128 + c16 * 16)));
            }
            uint32_t br[4][4];
            #pragma unroll
            for (int nt2 = 0; nt2 < 4; ++nt2) {
                const int row = wn + nt2 * 16 + (lg >> 1) * 8 + lr;
                const int c16 = 2 * kk + (lg & 1);
                ldsm4(br[nt2], sb + A_STAGE_BYTES + swz((uint32_t)(row * 128 + c16 * 16)));
            }
            #pragma unroll
            for (int mt = 0; mt < 4; ++mt)
                #pragma unroll
                for (int nt = 0; nt < 8; ++nt) {
                    const int nt2 = nt >> 1, hi = (nt & 1) * 2;
                    mma16(acc[mt][nt], ar[mt], br[nt2][hi], br[nt2][hi + 1]);
                }
        }
    }

    const int r4 = lane >> 2;
    const int c4 = lane & 3;

    auto epi = [&](int pos, int col, float v0, float v1) {
        v0 *= INVSQ_; v1 *= INVSQ_;
        if (MODE == 0) {
            C[(size_t)pos * N + col]     = v0 + bias1[col]     + bias2[col];
            C[(size_t)pos * N + col + 1] = v1 + bias1[col + 1] + bias2[col + 1];
        } else if (MODE == 1) {
            const size_t off = (size_t)pos * N + col;
            C[off]     = v0 + addsrc[off];
            C[off + 1] = v1 + addsrc[off + 1];
        } else if (MODE == 2 || MODE == 5) {
            const float w0 = fmaxf(v0 + bias1[col], 0.f);
            const float w1 = fmaxf(v1 + bias1[col + 1], 0.f);
            const float f0 = SCALE_ * w0, f1 = SCALE_ * w1;
            const __half h0 = __float2half_rn(f0), h1 = __float2half_rn(f1);
            const __half l0 = __float2half_rn(f0 - __half2float(h0));
            const __half l1 = __float2half_rn(f1 - __half2float(h1));
            if (MODE == 2) {          // activation triple [hi|hi|lo], stride KP_
                __half* o = out3 + (size_t)pos * KP_ + col;
                o[0] = h0;           o[1] = h1;
                o[H_] = h0;          o[H_ + 1] = h1;
                o[2 * H_] = l0;      o[2 * H_ + 1] = l1;
            } else {                  // activation pair [hi|lo], stride KP2_
                __half* o = out3 + (size_t)pos * KP2_ + col;
                o[0] = h0;           o[1] = h1;
                o[H_] = l0;          o[H_ + 1] = l1;
            }
        } else { // MODE 3
            const int crow = rowidC[pos];
            const float sc = rowscale[(size_t)crow * rs_stride];
            const size_t off = (size_t)crow * N + col;
            C[off]     = C[off]     + sc * (v0 + bias1[col]);
            C[off + 1] = C[off + 1] + sc * (v1 + bias1[col + 1]);
        }
    };

    #pragma unroll
    for (int mt = 0; mt < 4; ++mt) {
        #pragma unroll
        for (int nt = 0; nt < 8; ++nt) {
            const int pos = m0 + wm + mt * 16 + r4;
            const int col = n0 + wn + nt * 8 + c4 * 2;
            epi(pos,     col, acc[mt][nt][0], acc[mt][nt][1]);
            epi(pos + 8, col, acc[mt][nt][2], acc[mt][nt][3]);
        }
    }
}

// ---------------- vectorized conversions (one block per 768-wide row) -----------
__device__ __forceinline__ void split16(float f, __half& hi, __half& lo) {
    hi = __float2half_rn(f);
    lo = __float2half_rn(f - __half2float(hi));
}

// weight triple [hi|lo|hi], stride KP_
__global__ void convW3v(const float* __restrict__ src, __half* __restrict__ dst) {
    const int r = blockIdx.x;
    const int k4 = threadIdx.x * 4;    // 192 threads
    const float4 f = *(const float4*)(src + (size_t)r * H_ + k4);
    __half h0,h1,h2,h3,l0,l1,l2,l3;
    split16(SCALE_*f.x,h0,l0); split16(SCALE_*f.y,h1,l1);
    split16(SCALE_*f.z,h2,l2); split16(SCALE_*f.w,h3,l3);
    const __half2 H0 = __halves2half2(h0,h1), H1 = __halves2half2(h2,h3);
    const __half2 L0 = __halves2half2(l0,l1), L1 = __halves2half2(l2,l3);
    __half* o = dst + (size_t)r * KP_;
    *(__half2*)(o + k4) = H0;            *(__half2*)(o + k4 + 2) = H1;
    *(__half2*)(o + H_ + k4) = L0;       *(__half2*)(o + H_ + k4 + 2) = L1;
    *(__half2*)(o + 2*H_ + k4) = H0;     *(__half2*)(o + 2*H_ + k4 + 2) = H1;
}
// activation triple [hi|hi|lo], stride KP_
__global__ void convA3v(const float* __restrict__ src, __half* __restrict__ dst) {
    const int r = blockIdx.x;
    const int k4 = threadIdx.x * 4;
    const float4 f = *(const float4*)(src + (size_t)r * H_ + k4);
    __half h0,h1,h2,h3,l0,l1,l2,l3;
    split16(SCALE_*f.x,h0,l0); split16(SCALE_*f.y,h1,l1);
    split16(SCALE_*f.z,h2,l2); split16(SCALE_*f.w,h3,l3);
    const __half2 H0 = __halves2half2(h0,h1), H1 = __halves2half2(h2,h3);
    const __half2 L0 = __halves2half2(l0,l1), L1 = __halves2half2(l2,l3);
    __half* o = dst + (size_t)r * KP_;
    *(__half2*)(o + k4) = H0;            *(__half2*)(o + k4 + 2) = H1;
    *(__half2*)(o + H_ + k4) = H0;       *(__half2*)(o + H_ + k4 + 2) = H1;
    *(__half2*)(o + 2*H_ + k4) = L0;     *(__half2*)(o + 2*H_ + k4 + 2) = L1;
}
// weight pair [hi|hi], stride KP2_
__global__ void convW2v(const float* __restrict__ src, __half* __restrict__ dst) {
    const int r = blockIdx.x;
    const int k4 = threadIdx.x * 4;
    const float4 f = *(const float4*)(src + (size_t)r * H_ + k4);
    const __half2 H0 = __halves2half2(__float2half_rn(SCALE_*f.x), __float2half_rn(SCALE_*f.y));
    const __half2 H1 = __halves2half2(__float2half_rn(SCALE_*f.z), __float2half_rn(SCALE_*f.w));
    __half* o = dst + (size_t)r * KP2_;
    *(__half2*)(o + k4) = H0;        *(__half2*)(o + k4 + 2) = H1;
    *(__half2*)(o + H_ + k4) = H0;   *(__half2*)(o + H_ + k4 + 2) = H1;
}
// activation pair [hi|lo], stride KP2_
__global__ void convA2v(const float* __restrict__ src, __half* __restrict__ dst) {
    const int r = blockIdx.x;
    const int k4 = threadIdx.x * 4;
    const float4 f = *(const float4*)(src + (size_t)r * H_ + k4);
    __half h0,h1,h2,h3,l0,l1,l2,l3;
    split16(SCALE_*f.x,h0,l0); split16(SCALE_*f.y,h1,l1);
    split16(SCALE_*f.z,h2,l2); split16(SCALE_*f.w,h3,l3);
    __half* o = dst + (size_t)r * KP2_;
    *(__half2*)(o + k4) = __halves2half2(h0,h1);
    *(__half2*)(o + k4 + 2) = __halves2half2(h2,h3);
    *(__half2*)(o + H_ + k4) = __halves2half2(l0,l1);
    *(__half2*)(o + H_ + k4 + 2) = __halves2half2(l2,l3);
}

__global__ void fill0(float* p, size_t n) {
    size_t i  = (size_t)blockIdx.x * blockDim.x + threadIdx.x;
    size_t st = (size_t)gridDim.x * blockDim.x;
    for (; i < n; i += st) p[i] = 0.f;
}

// ---------------- fused LSTM cell (384 thr, 2 elems/thread) ----------------
__global__ void lstm_cell(const float* __restrict__ gates,
                          const float* __restrict__ Whalt, const float* __restrict__ bhalt,
                          float* __restrict__ c, __half* __restrict__ h2,
                          float* __restrict__ hsum, float* __restrict__ hp,
                          float* __restrict__ rem)
{
    const int row = blockIdx.x;
    const int tid = threadIdx.x;           // 384
    const int j2  = tid * 2;
    const float* gr = gates + (size_t)row * G4_;
    const float2 gi = *(const float2*)(gr + j2);
    const float2 gf = *(const float2*)(gr + H_ + j2);
    const float2 gg = *(const float2*)(gr + 2 * H_ + j2);
    const float2 go = *(const float2*)(gr + 3 * H_ + j2);
    const size_t o = (size_t)row * H_ + j2;
    float2 cv = *(const float2*)(c + o);
    cv.x = sigf(gf.x) * cv.x + sigf(gi.x) * tanhf_fast(gg.x);
    cv.y = sigf(gf.y) * cv.y + sigf(gi.y) * tanhf_fast(gg.y);
    const float h0 = sigf(go.x) * tanhf_fast(cv.x);
    const float h1 = sigf(go.y) * tanhf_fast(cv.y);
    *(float2*)(c + o) = cv;
    float2 hs = *(const float2*)(hsum + o);
    hs.x += h0; hs.y += h1;
    *(float2*)(hsum + o) = hs;
    __half a0, a1, b0, b1;
    split16(SCALE_ * h0, a0, b0);
    split16(SCALE_ * h1, a1, b1);
    __half* hr = h2 + (size_t)row * KP_;
    const __half2 hh = __halves2half2(a0, a1);
    *(__half2*)(hr + j2) = hh;
    *(__half2*)(hr + H_ + j2) = hh;
    *(__half2*)(hr + 2 * H_ + j2) = __halves2half2(b0, b1);
    const float2 wv = *(const float2*)(Whalt + j2);
    float part = h0 * wv.x + h1 * wv.y;
    #pragma unroll
    for (int off = 16; off > 0; off >>= 1)
        part += __shfl_down_sync(0xffffffffu, part, off);
    __shared__ float red[12];
    if ((tid & 31) == 0) red[tid >> 5] = part;
    __syncthreads();
    if (tid == 0) {
        float s = 0.f;
        #pragma unroll
        for (int i = 0; i < 12; ++i) s += red[i];
        const float y = sigf(s + bhalt[0]);
        float hpv = hp[row];
        hpv = hpv + y * (1.f - hpv);
        hp[row] = hpv;
        rem[row] += 1.f - hpv;
    }
}

// ---------------- avg: fp32 x0 + activation triple (384 thr, 2/thr) -------------
__global__ void avg_kernel(const float* __restrict__ hsum, const float* __restrict__ rem,
                           float* __restrict__ x0, __half* __restrict__ x02)
{
    const int r = blockIdx.x;
    const int j2 = threadIdx.x * 2;
    const float rm = rem[r] * 0.1f;
    const size_t o = (size_t)r * H_ + j2;
    const float2 hs = *(const float2*)(hsum + o);
    const float v0 = rm * hs.x, v1 = rm * hs.y;
    *(float2*)(x0 + o) = make_float2(v0, v1);
    __half a0, a1, b0, b1;
    split16(SCALE_ * v0, a0, b0);
    split16(SCALE_ * v1, a1, b1);
    __half* od = x02 + (size_t)r * KP_;
    const __half2 hh = __halves2half2(a0, a1);
    *(__half2*)(od + j2) = hh;
    *(__half2*)(od + H_ + j2) = hh;
    *(__half2*)(od + 2 * H_ + j2) = __halves2half2(b0, b1);
}

// ---------------- router ----------------
__global__ void router(const float* __restrict__ x, const float* __restrict__ Wg,
                       const float* __restrict__ bg, float* __restrict__ w)
{
    const int row = blockIdx.x;
    const int tid = threadIdx.x;   // 128
    const float* xr = x + (size_t)row * H_;
    float p0 = 0.f, p1 = 0.f, p2 = 0.f, p3 = 0.f;
    for (int k = tid; k < H_; k += 128) {
        const float xv = xr[k];
        p0 += xv * Wg[k];
        p1 += xv * Wg[H_ + k];
        p2 += xv * Wg[2 * H_ + k];
        p3 += xv * Wg[3 * H_ + k];
    }
    __shared__ float red[4][128];
    red[0][tid] = p0; red[1][tid] = p1; red[2][tid] = p2; red[3][tid] = p3;
    __syncthreads();
    #pragma unroll
    for (int s = 64; s > 0; s >>= 1) {
        if (tid < s) {
            #pragma unroll
            for (int e = 0; e < 4; ++e) red[e][tid] += red[e][tid + s];
        }
        __syncthreads();
    }
    if (tid == 0) {
        float lg[4];
        #pragma unroll
        for (int e = 0; e < 4; ++e) lg[e] = red[e][0] + bg[e];
        int i1 = 0; float m1 = lg[0];
        #pragma unroll
        for (int e = 1; e < 4; ++e) if (lg[e] > m1) { m1 = lg[e]; i1 = e; }
        int i2 = -1; float m2 = -3.4e38f;
        #pragma unroll
        for (int e = 0; e < 4; ++e) if (e != i1 && lg[e] > m2) { m2 = lg[e]; i2 = e; }
        const float e2 = expf(m2 - m1);
        const float s  = 1.f + e2;
        float out4[4] = {0.f, 0.f, 0.f, 0.f};
        out4[i1] = 1.f / s;
        out4[i2] = e2 / s;
        #pragma unroll
        for (int e = 0; e < 4; ++e) w[row * 4 + e] = out4[e];
    }
}

// ---------------- sparse-MoE list building ----------------
__global__ void reset_cnt(int* cnt) {
    if (threadIdx.x < E_) cnt[threadIdx.x] = 0;
}
__global__ void build_lists(const float* __restrict__ w, int* __restrict__ cnt,
                            int* __restrict__ rowid)
{
    int r = blockIdx.x * blockDim.x + threadIdx.x;
    const int st = gridDim.x * blockDim.x;
    for (; r < B_; r += st) {
        #pragma unroll
        for (int e = 0; e < E_; ++e) {
            if (w[(size_t)r * 4 + e] > 0.f) {
                const int slot = atomicAdd(&cnt[e], 1);
                rowid[(size_t)e * BP_ + slot] = r;
            }
        }
    }
}
__global__ void pad_lists(const int* __restrict__ cnt, int* __restrict__ cntpad,
                          int* __restrict__ rowid)
{
    const int tid = threadIdx.x;   // 128
    for (int e = 0; e < E_; ++e) {
        const int n  = cnt[e];
        const int np = ((n + BM - 1) / BM) * BM;
        for (int i = n + tid; i < np; i += 128) rowid[(size_t)e * BP_ + i] = B_;
        if (tid == 0) cntpad[e] = np;
    }
}

// ---------------- final LayerNorm ----------------
__global__ void layernorm(const float* __restrict__ x, const float* __restrict__ gamma,
                          const float* __restrict__ beta, float* __restrict__ out)
{
    const int row = blockIdx.x;
    const int tid = threadIdx.x;   // 256
    const float* xr = x + (size_t)row * D_;
    float v[D_ / 256];
    float s = 0.f;
    #pragma unroll
    for (int it = 0; it < D_ / 256; ++it) { v[it] = xr[tid + it * 256]; s += v[it]; }
    __shared__ float red[256];
    red[tid] = s;
    __syncthreads();
    #pragma unroll
    for (int st = 128; st > 0; st >>= 1) {
        if (tid < st) red[tid] += red[tid + st];
        __syncthreads();
    }
    const float mu = red[0] / (float)D_;
    __syncthreads();
    float s2 = 0.f;
    #pragma unroll
    for (int it = 0; it < D_ / 256; ++it) { const float d = v[it] - mu; s2 += d * d; }
    red[tid] = s2;
    __syncthreads();
    #pragma unroll
    for (int st = 128; st > 0; st >>= 1) {
        if (tid < st) red[tid] += red[tid + st];
        __syncthreads();
    }
    const float var = red[0] / (float)D_;
    const float inv = rsqrtf(var + 1e-5f);
    #pragma unroll
    for (int it = 0; it < D_ / 256; ++it) {
        const int cc = tid + it * 256;
        out[(size_t)row * D_ + cc] = (v[it] - mu) * inv * gamma[cc] + beta[cc];
    }
}

// ---------------- host ----------------
struct Ptrs {
    __half *act2, *hmid2, *Wi2, *Wh2, *W12, *W22, *W12b, *W22b;
    float *xWi, *gates, *c, *hsum, *x0, *accA, *accB, *hp, *rem, *w;
    int *rowid, *cnt, *cntpad;
};

static Ptrs get_ptrs() {
    static Ptrs P = [] {
        Ptrs q{};
        cudaGetSymbolAddress((void**)&q.act2,   g_act2);
        cudaGetSymbolAddress((void**)&q.hmid2,  g_hmid2);
        cudaGetSymbolAddress((void**)&q.Wi2,    g_Wi2);
        cudaGetSymbolAddress((void**)&q.Wh2,    g_Wh2);
        cudaGetSymbolAddress((void**)&q.W12,    g_W12);
        cudaGetSymbolAddress((void**)&q.W22,    g_W22);
        cudaGetSymbolAddress((void**)&q.W12b,   g_W12b);
        cudaGetSymbolAddress((void**)&q.W22b,   g_W22b);
        cudaGetSymbolAddress((void**)&q.xWi,    g_xWi);
        cudaGetSymbolAddress((void**)&q.gates,  g_gates);
        cudaGetSymbolAddress((void**)&q.c,      g_c);
        cudaGetSymbolAddress((void**)&q.hsum,   g_hsum);
        cudaGetSymbolAddress((void**)&q.x0,     g_x0);
        cudaGetSymbolAddress((void**)&q.accA,   g_accA);
        cudaGetSymbolAddress((void**)&q.accB,   g_accB);
        cudaGetSymbolAddress((void**)&q.hp,     g_hp);
        cudaGetSymbolAddress((void**)&q.rem,    g_rem);
        cudaGetSymbolAddress((void**)&q.w,      g_w);
        cudaGetSymbolAddress((void**)&q.rowid,  g_rowid);
        cudaGetSymbolAddress((void**)&q.cnt,    g_cnt);
        cudaGetSymbolAddress((void**)&q.cntpad, g_cntpad);
        return q;
    }();
    return P;
}

extern "C" void kernel_launch(void* const* d_in, const int* in_sizes, int n_in,
                              void* d_out, int out_size)
{
    const float* x     = (const float*)d_in[0];
    const float* Wi    = (const float*)d_in[1];
    const float* Wh    = (const float*)d_in[2];
    const float* bi    = (const float*)d_in[3];
    const float* bh    = (const float*)d_in[4];
    const float* Whalt = (const float*)d_in[5];
    const float* bhalt = (const float*)d_in[6];
    const float* gateW = (const float*)d_in[7];
    const float* gateb = (const float*)d_in[8];
    const float* W1    = (const float*)d_in[9];
    const float* b1    = (const float*)d_in[10];
    const float* W2    = (const float*)d_in[11];
    const float* b2    = (const float*)d_in[12];
    const float* gamma = (const float*)d_in[13];
    const float* beta  = (const float*)d_in[14];
    float* out = (float*)d_out;

    Ptrs P = get_ptrs();

    cudaFuncSetAttribute((const void*)tgemm<0>, cudaFuncAttributeMaxDynamicSharedMemorySize, SMEM_DYN);
    cudaFuncSetAttribute((const void*)tgemm<1>, cudaFuncAttributeMaxDynamicSharedMemorySize, SMEM_DYN);
    cudaFuncSetAttribute((const void*)tgemm<2>, cudaFuncAttributeMaxDynamicSharedMemorySize, SMEM_DYN);
    cudaFuncSetAttribute((const void*)tgemm<3>, cudaFuncAttributeMaxDynamicSharedMemorySize, SMEM_DYN);
    cudaFuncSetAttribute((const void*)tgemm<5>, cudaFuncAttributeMaxDynamicSharedMemorySize, SMEM_DYN);

    const size_t lvl2off = (size_t)4 * H_ * H_;   // level-2 weight block offset

    // conversions
    convW3v<<<G4_, 192>>>(Wi, P.Wi2);
    convW3v<<<G4_, 192>>>(Wh, P.Wh2);
    convW3v<<<4 * H_, 192>>>(W1, P.W12);
    convW3v<<<4 * D_, 192>>>(W2, P.W22);
    convW2v<<<4 * H_, 192>>>(W1 + lvl2off, P.W12b);
    convW2v<<<4 * D_, 192>>>(W2 + lvl2off, P.W22b);
    convA3v<<<B_, 192>>>(x, P.act2);

    // zero recurrent state
    fill0<<<2048, 256>>>(P.c,    (size_t)B_ * H_);
    fill0<<<2048, 256>>>(P.hsum, (size_t)B_ * H_);
    fill0<<<64,   256>>>(P.hp,   (size_t)B_);
    fill0<<<64,   256>>>(P.rem,  (size_t)B_);

    // xWi = x @ Wi^T + bi + bh
    dim3 gridG(G4_ / BN, B_ / BM);
    tgemm<0><<<gridG, 256, SMEM_DYN>>>(P.act2, P.Wi2, P.xWi, G4_, KP_,
                                       bi, bh, nullptr, nullptr, 0, nullptr,
                                       nullptr, nullptr, nullptr);

    for (int t = 0; t < T_; ++t) {
        const float* gptr;
        if (t == 0) {
            gptr = P.xWi;
        } else {
            tgemm<1><<<gridG, 256, SMEM_DYN>>>(P.act2, P.Wh2, P.gates, G4_, KP_,
                                               nullptr, nullptr, P.xWi, nullptr, 0, nullptr,
                                               nullptr, nullptr, nullptr);
            gptr = P.gates;
        }
        lstm_cell<<<B_, 384>>>(gptr, Whalt, bhalt, P.c, P.act2, P.hsum, P.hp, P.rem);
    }

    avg_kernel<<<B_, 384>>>(P.hsum, P.rem, P.x0, P.act2);

    dim3 gridH(H_ / BN, B_ / BM);

    // ---- level 1 (split-3, flip-safe: feeds level-2 router) ----
    reset_cnt<<<1, 32>>>(P.cnt);
    router<<<B_, 128>>>(P.x0, gateW, gateb, P.w);
    build_lists<<<64, 256>>>(P.w, P.cnt, P.rowid);
    pad_lists<<<1, 128>>>(P.cnt, P.cntpad, P.rowid);
    fill0<<<2048, 256>>>(P.accA, (size_t)BP_ * D_);
    for (int e = 0; e < E_; ++e) {
        tgemm<2><<<gridH, 256, SMEM_DYN>>>(P.act2, P.W12 + (size_t)e * H_ * KP_, nullptr, H_, KP_,
                                           b1 + (size_t)e * H_, nullptr, nullptr, nullptr, 0,
                                           P.hmid2,
                                           P.cntpad + e, P.rowid + (size_t)e * BP_, nullptr);
        tgemm<3><<<gridH, 256, SMEM_DYN>>>(P.hmid2, P.W22 + (size_t)e * D_ * KP_, P.accA, D_, KP_,
                                           b2 + (size_t)e * D_, nullptr, nullptr, P.w + e, E_,
                                           nullptr,
                                           P.cntpad + e, nullptr, P.rowid + (size_t)e * BP_);
    }

    // ---- level 2 (split-2: only final-output precision needed) ----
    convA2v<<<B_, 192>>>(P.accA, P.act2);          // packed pair, stride KP2_
    __half* hmidP = (__half*)P.gates;              // reuse gates buffer
    reset_cnt<<<1, 32>>>(P.cnt);
    router<<<B_, 128>>>(P.accA, gateW + (size_t)E_ * H_, gateb + E_, P.w);
    build_lists<<<64, 256>>>(P.w, P.cnt, P.rowid);
    pad_lists<<<1, 128>>>(P.cnt, P.cntpad, P.rowid);
    fill0<<<2048, 256>>>(P.accB, (size_t)BP_ * D_);
    for (int e = 0; e < E_; ++e) {
        tgemm<5><<<gridH, 256, SMEM_DYN>>>(P.act2, P.W12b + (size_t)e * H_ * KP2_, nullptr, H_, KP2_,
                                           b1 + (size_t)(E_ + e) * H_, nullptr, nullptr, nullptr, 0,
                                           hmidP,
                                           P.cntpad + e, P.rowid + (size_t)e * BP_, nullptr);
        tgemm<3><<<gridH, 256, SMEM_DYN>>>(hmidP, P.W22b + (size_t)e * D_ * KP2_, P.accB, D_, KP2_,
                                           b2 + (size_t)(E_ + e) * D_, nullptr, nullptr, P.w + e, E_,
                                           nullptr,
                                           P.cntpad + e, nullptr, P.rowid + (size_t)e * BP_);
    }

    layernorm<<<B_, 256>>>(P.accB, gamma, beta, out);
}

// round 17
// speedup vs baseline: 1.6798x; 1.0723x over previous
#include <cuda_runtime.h>
#include <cuda_fp16.h>
#include <math.h>
#include <stdint.h>
#include <stddef.h>

#define B_   16384
#define BP_  (B_ + 128)
#define D_   768
#define H_   768
#define G4_  3072
#define KP_  2304   // split-3 K
#define KP2_ 1536   // split-2 K
#define E_   4
#define T_   10

#define SCALE_  32.0f
#define INVSQ_  (1.0f / 1024.0f)
#define RMASK_  0x3FFFFFFF

// GEMM tiling
#define BM 128
#define BN 256
#define BK 64
#define NSTG 3
#define A_STAGE_BYTES (BM * 128)
#define STAGE_BYTES ((BM + BN) * 128)
#define SMEM_DYN (NSTG * STAGE_BYTES)

// ---------------- scratch (static device globals; no allocation) ----------------
__device__ __align__(128) __half g_act2 [(size_t)BP_ * KP_];        // activations
__device__ __align__(128) __half g_hmid2[(size_t)E_ * BP_ * KP_];   // per-expert hmid regions
__device__ __align__(128) __half g_Wi2  [(size_t)G4_ * KP_];
__device__ __align__(128) __half g_Wh2  [(size_t)G4_ * KP_];
__device__ __align__(128) __half g_W12  [(size_t)E_ * H_ * KP_];    // lvl-1 triple
__device__ __align__(128) __half g_W22  [(size_t)E_ * D_ * KP_];
__device__ __align__(128) __half g_W12b [(size_t)E_ * H_ * KP2_];   // lvl-2 pair
__device__ __align__(128) __half g_W22b [(size_t)E_ * D_ * KP2_];
__device__ __align__(128) float g_xWi [(size_t)B_ * G4_];           // also lvl-2 slot pair
__device__ __align__(128) float g_gates[(size_t)B_ * G4_];
__device__ __align__(128) float g_c   [(size_t)B_ * H_];
__device__ __align__(128) float g_hsum[(size_t)B_ * H_];
__device__ __align__(128) float g_x0  [(size_t)B_ * H_];
__device__ __align__(128) float g_acc1[(size_t)2 * BP_ * D_];       // lvl-1 slot pair
__device__ float g_hp  [B_];
__device__ float g_rem [B_];
__device__ float g_w   [BP_ * E_];          // pad rows stay 0
__device__ int   g_rowid[E_ * BP_];
__device__ int   g_cnt  [E_];
__device__ int   g_cntpad[E_];

__device__ __forceinline__ float sigf(float x) {
    return __fdividef(1.f, 1.f + __expf(-x));
}
__device__ __forceinline__ float tanhf_fast(float x) {
    const float e = __expf(-2.f * fabsf(x));
    return copysignf(__fdividef(1.f - e, 1.f + e), x);
}

__device__ __forceinline__ uint32_t s2u(const void* p) {
    uint32_t a;
    asm("{ .reg .u64 t; cvta.to.shared.u64 t, %1; cvt.u32.u64 %0, t; }" : "=r"(a) : "l"(p));
    return a;
}
__device__ __forceinline__ uint32_t swz(uint32_t off) { return off ^ ((off >> 3) & 0x70); }

__device__ __forceinline__ void ldsm4(uint32_t* r, uint32_t addr) {
    asm volatile("ldmatrix.sync.aligned.m8n8.x4.shared.b16 {%0,%1,%2,%3}, [%4];"
                 : "=r"(r[0]), "=r"(r[1]), "=r"(r[2]), "=r"(r[3]) : "r"(addr));
}

__device__ __forceinline__ void mma16(float* d, const uint32_t* a, uint32_t b0, uint32_t b1) {
    asm volatile(
        "mma.sync.aligned.m16n8k16.row.col.f32.f16.f16.f32 "
        "{%0,%1,%2,%3}, {%4,%5,%6,%7}, {%8,%9}, {%0,%1,%2,%3};"
        : "+f"(d[0]), "+f"(d[1]), "+f"(d[2]), "+f"(d[3])
        : "r"(a[0]), "r"(a[1]), "r"(a[2]), "r"(a[3]), "r"(b0), "r"(b1));
}

// ---------------- fp16 split GEMM (z-batched over experts) ----------------------
// MODE 0: C = v + bias1 + bias2                       (xWi producer; grid.z=1)
// MODE 1: C = v + addsrc                              (recurrent gates; grid.z=1)
// MODE 2: hmid triple [hi|hi|lo] = relu(v + bias1); A gathered; z = expert
// MODE 5: hmid pair   [hi|lo]    = relu(v + bias1); A gathered; z = expert
// MODE 3: C[(slot*BP_+crow)] = wts[crow*4+z] * (v + bias1)   (pure scatter write)
template<int MODE>
__global__ __launch_bounds__(256, 1)
void tgemm(const __half* __restrict__ A, const __half* __restrict__ W,
           float* __restrict__ C, int N, int Kp,
           const float* __restrict__ bias1, const float* __restrict__ bias2,
           const float* __restrict__ addsrc,
           const float* __restrict__ wts,
           __half* __restrict__ out3,
           const int* __restrict__ cntpad, const int* __restrict__ rowid,
           size_t zA, size_t zW, int zB, size_t zOut)
{
    const int z = blockIdx.z;
    if (MODE == 2 || MODE == 3 || MODE == 5) {
        if ((int)(blockIdx.y * BM) >= cntpad[z]) return;
    }
    const __half* Az = A + (size_t)z * zA;
    const __half* Wz = W + (size_t)z * zW;
    const float*  b1z = bias1 + (size_t)z * zB;
    __half* o3z = (MODE == 2 || MODE == 5) ? out3 + (size_t)z * zOut : nullptr;
    const int* rl = (MODE == 2 || MODE == 3 || MODE == 5) ? rowid + (size_t)z * BP_ : nullptr;

    extern __shared__ char smem[];
    const int tid  = threadIdx.x;
    const int lane = tid & 31;
    const int wid  = tid >> 5;
    const int m0 = blockIdx.y * BM;
    const int n0 = blockIdx.x * BN;
    const int wm = (wid >> 2) * 64;
    const int wn = (wid & 3) * 64;
    const uint32_t su = s2u(smem);

    const int NCH = Kp / BK;

    auto produce = [&](int p) {
        const uint32_t sb = su + (uint32_t)(p % NSTG) * STAGE_BYTES;
        #pragma unroll
        for (int i = 0; i < 12; ++i) {
            const int g = i * 256 + tid;
            uint32_t dst;
            const __half* src;
            if (g < 1024) {
                const int row = g >> 3, c = g & 7;
                const int arow = (MODE == 2 || MODE == 5)
                               ? (rl[m0 + row] & RMASK_) : (m0 + row);
                dst = sb + swz((uint32_t)(row * 128 + c * 16));
                src = Az + (size_t)arow * Kp + (size_t)p * BK + c * 8;
            } else {
                const int gg = g - 1024;
                const int row = gg >> 3, c = gg & 7;
                dst = sb + A_STAGE_BYTES + swz((uint32_t)(row * 128 + c * 16));
                src = Wz + (size_t)(n0 + row) * Kp + (size_t)p * BK + c * 8;
            }
            asm volatile("cp.async.cg.shared.global [%0], [%1], 16;" :: "r"(dst), "l"(src));
        }
        asm volatile("cp.async.commit_group;" ::: "memory");
    };

    float acc[4][8][4];
    #pragma unroll
    for (int mt = 0; mt < 4; ++mt)
        #pragma unroll
        for (int nt = 0; nt < 8; ++nt)
            #pragma unroll
            for (int q = 0; q < 4; ++q) acc[mt][nt][q] = 0.f;

    produce(0);
    produce(1);

    const int lr = lane & 7;
    const int lg = lane >> 3;

    for (int s = 0; s < NCH; ++s) {
        asm volatile("cp.async.wait_group 1;" ::: "memory");
        __syncthreads();
        if (s + 2 < NCH) produce(s + 2);

        const uint32_t sb = su + (uint32_t)(s % NSTG) * STAGE_BYTES;

        #pragma unroll
        for (int kk = 0; kk < 4; ++kk) {
            uint32_t ar[4][4];
            #pragma unroll
            for (int mt = 0; mt < 4; ++mt) {
                const int row = wm + mt * 16 + (lg & 1) * 8 + lr;
                const int c16 = 2 * kk + (lg >> 1);
                ldsm4(ar[mt], sb + swz((uint32_t)(row * 128 + c16 * 16)));
            }
            uint32_t br[4][4];
            #pragma unroll
            for (int nt2 = 0; nt2 < 4; ++nt2) {
                const int row = wn + nt2 * 16 + (lg >> 1) * 8 + lr;
                const int c16 = 2 * kk + (lg & 1);
                ldsm4(br[nt2], sb + A_STAGE_BYTES + swz((uint32_t)(row * 128 + c16 * 16)));
            }
            #pragma unroll
            for (int mt = 0; mt < 4; ++mt)
                #pragma unroll
                for (int nt = 0; nt < 8; ++nt) {
                    const int nt2 = nt >> 1, hi = (nt & 1) * 2;
                    mma16(acc[mt][nt], ar[mt], br[nt2][hi], br[nt2][hi + 1]);
                }
        }
    }

    const int r4 = lane >> 2;
    const int c4 = lane & 3;

    auto epi = [&](int pos, int col, float v0, float v1) {
        v0 *= INVSQ_; v1 *= INVSQ_;
        if (MODE == 0) {
            C[(size_t)pos * N + col]     = v0 + b1z[col]     + bias2[col];
            C[(size_t)pos * N + col + 1] = v1 + b1z[col + 1] + bias2[col + 1];
        } else if (MODE == 1) {
            const size_t off = (size_t)pos * N + col;
            C[off]     = v0 + addsrc[off];
            C[off + 1] = v1 + addsrc[off + 1];
        } else if (MODE == 2 || MODE == 5) {
            const float w0 = fmaxf(v0 + b1z[col], 0.f);
            const float w1 = fmaxf(v1 + b1z[col + 1], 0.f);
            const float f0 = SCALE_ * w0, f1 = SCALE_ * w1;
            const __half h0 = __float2half_rn(f0), h1 = __float2half_rn(f1);
            const __half l0 = __float2half_rn(f0 - __half2float(h0));
            const __half l1 = __float2half_rn(f1 - __half2float(h1));
            if (MODE == 2) {
                __half* o = o3z + (size_t)pos * KP_ + col;
                o[0] = h0;           o[1] = h1;
                o[H_] = h0;          o[H_ + 1] = h1;
                o[2 * H_] = l0;      o[2 * H_ + 1] = l1;
            } else {
                __half* o = o3z + (size_t)pos * KP2_ + col;
                o[0] = h0;           o[1] = h1;
                o[H_] = l0;          o[H_ + 1] = l1;
            }
        } else { // MODE 3: slot-separated pure write
            const int id   = rl[pos];
            const int crow = id & RMASK_;
            const int slot = (id >> 30) & 1;
            const float sc = wts[(size_t)crow * 4 + z];
            const size_t off = ((size_t)slot * BP_ + crow) * N + col;
            C[off]     = sc * (v0 + b1z[col]);
            C[off + 1] = sc * (v1 + b1z[col + 1]);
        }
    };

    #pragma unroll
    for (int mt = 0; mt < 4; ++mt) {
        #pragma unroll
        for (int nt = 0; nt < 8; ++nt) {
            const int pos = m0 + wm + mt * 16 + r4;
            const int col = n0 + wn + nt * 8 + c4 * 2;
            epi(pos,     col, acc[mt][nt][0], acc[mt][nt][1]);
            epi(pos + 8, col, acc[mt][nt][2], acc[mt][nt][3]);
        }
    }
}

// ---------------- vectorized conversions ----------------
__device__ __forceinline__ void split16(float f, __half& hi, __half& lo) {
    hi = __float2half_rn(f);
    lo = __float2half_rn(f - __half2float(hi));
}

__global__ void convW3v(const float* __restrict__ src, __half* __restrict__ dst) {
    const int r = blockIdx.x;
    const int k4 = threadIdx.x * 4;    // 192 threads
    const float4 f = *(const float4*)(src + (size_t)r * H_ + k4);
    __half h0,h1,h2,h3,l0,l1,l2,l3;
    split16(SCALE_*f.x,h0,l0); split16(SCALE_*f.y,h1,l1);
    split16(SCALE_*f.z,h2,l2); split16(SCALE_*f.w,h3,l3);
    const __half2 H0 = __halves2half2(h0,h1), H1 = __halves2half2(h2,h3);
    const __half2 L0 = __halves2half2(l0,l1), L1 = __halves2half2(l2,l3);
    __half* o = dst + (size_t)r * KP_;
    *(__half2*)(o + k4) = H0;            *(__half2*)(o + k4 + 2) = H1;
    *(__half2*)(o + H_ + k4) = L0;       *(__half2*)(o + H_ + k4 + 2) = L1;
    *(__half2*)(o + 2*H_ + k4) = H0;     *(__half2*)(o + 2*H_ + k4 + 2) = H1;
}
__global__ void convA3v(const float* __restrict__ src, __half* __restrict__ dst) {
    const int r = blockIdx.x;
    const int k4 = threadIdx.x * 4;
    const float4 f = *(const float4*)(src + (size_t)r * H_ + k4);
    __half h0,h1,h2,h3,l0,l1,l2,l3;
    split16(SCALE_*f.x,h0,l0); split16(SCALE_*f.y,h1,l1);
    split16(SCALE_*f.z,h2,l2); split16(SCALE_*f.w,h3,l3);
    const __half2 H0 = __halves2half2(h0,h1), H1 = __halves2half2(h2,h3);
    const __half2 L0 = __halves2half2(l0,l1), L1 = __halves2half2(l2,l3);
    __half* o = dst + (size_t)r * KP_;
    *(__half2*)(o + k4) = H0;            *(__half2*)(o + k4 + 2) = H1;
    *(__half2*)(o + H_ + k4) = H0;       *(__half2*)(o + H_ + k4 + 2) = H1;
    *(__half2*)(o + 2*H_ + k4) = L0;     *(__half2*)(o + 2*H_ + k4 + 2) = L1;
}
__global__ void convW2v(const float* __restrict__ src, __half* __restrict__ dst) {
    const int r = blockIdx.x;
    const int k4 = threadIdx.x * 4;
    const float4 f = *(const float4*)(src + (size_t)r * H_ + k4);
    const __half2 H0 = __halves2half2(__float2half_rn(SCALE_*f.x), __float2half_rn(SCALE_*f.y));
    const __half2 H1 = __halves2half2(__float2half_rn(SCALE_*f.z), __float2half_rn(SCALE_*f.w));
    __half* o = dst + (size_t)r * KP2_;
    *(__half2*)(o + k4) = H0;        *(__half2*)(o + k4 + 2) = H1;
    *(__half2*)(o + H_ + k4) = H0;   *(__half2*)(o + H_ + k4 + 2) = H1;
}
// pair conversion from slot-sum: dst[r] = split2(s0[r]+s1[r])
__global__ void convA2v2(const float* __restrict__ s0, const float* __restrict__ s1,
                         __half* __restrict__ dst) {
    const int r = blockIdx.x;
    const int k4 = threadIdx.x * 4;
    const float4 a = *(const float4*)(s0 + (size_t)r * D_ + k4);
    const float4 b = *(const float4*)(s1 + (size_t)r * D_ + k4);
    const float fx = a.x + b.x, fy = a.y + b.y, fz = a.z + b.z, fw = a.w + b.w;
    __half h0,h1,h2,h3,l0,l1,l2,l3;
    split16(SCALE_*fx,h0,l0); split16(SCALE_*fy,h1,l1);
    split16(SCALE_*fz,h2,l2); split16(SCALE_*fw,h3,l3);
    __half* o = dst + (size_t)r * KP2_;
    *(__half2*)(o + k4) = __halves2half2(h0,h1);
    *(__half2*)(o + k4 + 2) = __halves2half2(h2,h3);
    *(__half2*)(o + H_ + k4) = __halves2half2(l0,l1);
    *(__half2*)(o + H_ + k4 + 2) = __halves2half2(l2,l3);
}

__global__ void fill0(float* p, size_t n) {
    size_t i  = (size_t)blockIdx.x * blockDim.x + threadIdx.x;
    size_t st = (size_t)gridDim.x * blockDim.x;
    for (; i < n; i += st) p[i] = 0.f;
}

// ---------------- fused LSTM cell (steps 0..8) ----------------
__global__ void lstm_cell(const float* __restrict__ gates,
                          const float* __restrict__ Whalt, const float* __restrict__ bhalt,
                          float* __restrict__ c, __half* __restrict__ h2,
                          float* __restrict__ hsum, float* __restrict__ hp,
                          float* __restrict__ rem)
{
    const int row = blockIdx.x;
    const int tid = threadIdx.x;           // 384
    const int j2  = tid * 2;
    const float* gr = gates + (size_t)row * G4_;
    const float2 gi = *(const float2*)(gr + j2);
    const float2 gf = *(const float2*)(gr + H_ + j2);
    const float2 gg = *(const float2*)(gr + 2 * H_ + j2);
    const float2 go = *(const float2*)(gr + 3 * H_ + j2);
    const size_t o = (size_t)row * H_ + j2;
    float2 cv = *(const float2*)(c + o);
    cv.x = sigf(gf.x) * cv.x + sigf(gi.x) * tanhf_fast(gg.x);
    cv.y = sigf(gf.y) * cv.y + sigf(gi.y) * tanhf_fast(gg.y);
    const float h0 = sigf(go.x) * tanhf_fast(cv.x);
    const float h1 = sigf(go.y) * tanhf_fast(cv.y);
    *(float2*)(c + o) = cv;
    float2 hs = *(const float2*)(hsum + o);
    hs.x += h0; hs.y += h1;
    *(float2*)(hsum + o) = hs;
    __half a0, a1, b0, b1;
    split16(SCALE_ * h0, a0, b0);
    split16(SCALE_ * h1, a1, b1);
    __half* hr = h2 + (size_t)row * KP_;
    const __half2 hh = __halves2half2(a0, a1);
    *(__half2*)(hr + j2) = hh;
    *(__half2*)(hr + H_ + j2) = hh;
    *(__half2*)(hr + 2 * H_ + j2) = __halves2half2(b0, b1);
    const float2 wv = *(const float2*)(Whalt + j2);
    float part = h0 * wv.x + h1 * wv.y;
    #pragma unroll
    for (int off = 16; off > 0; off >>= 1)
        part += __shfl_down_sync(0xffffffffu, part, off);
    __shared__ float red[12];
    if ((tid & 31) == 0) red[tid >> 5] = part;
    __syncthreads();
    if (tid == 0) {
        float s = 0.f;
        #pragma unroll
        for (int i = 0; i < 12; ++i) s += red[i];
        const float y = sigf(s + bhalt[0]);
        float hpv = hp[row];
        hpv = hpv + y * (1.f - hpv);
        hp[row] = hpv;
        rem[row] += 1.f - hpv;
    }
}

// ---------------- final LSTM step (t=9): fused avg -> x0 + act2 triple ----------
__global__ void lstm_cell_last(const float* __restrict__ gates,
                               const float* __restrict__ Whalt, const float* __restrict__ bhalt,
                               const float* __restrict__ c, const float* __restrict__ hsum,
                               const float* __restrict__ hp, const float* __restrict__ rem,
                               float* __restrict__ x0, __half* __restrict__ x02)
{
    const int row = blockIdx.x;
    const int tid = threadIdx.x;           // 384
    const int j2  = tid * 2;
    const float* gr = gates + (size_t)row * G4_;
    const float2 gi = *(const float2*)(gr + j2);
    const float2 gf = *(const float2*)(gr + H_ + j2);
    const float2 gg = *(const float2*)(gr + 2 * H_ + j2);
    const float2 go = *(const float2*)(gr + 3 * H_ + j2);
    const size_t o = (size_t)row * H_ + j2;
    float2 cv = *(const float2*)(c + o);
    cv.x = sigf(gf.x) * cv.x + sigf(gi.x) * tanhf_fast(gg.x);
    cv.y = sigf(gf.y) * cv.y + sigf(gi.y) * tanhf_fast(gg.y);
    const float h0 = sigf(go.x) * tanhf_fast(cv.x);
    const float h1 = sigf(go.y) * tanhf_fast(cv.y);
    const float2 hsold = *(const float2*)(hsum + o);
    const float hs0 = hsold.x + h0, hs1 = hsold.y + h1;
    const float2 wv = *(const float2*)(Whalt + j2);
    float part = h0 * wv.x + h1 * wv.y;
    #pragma unroll
    for (int off = 16; off > 0; off >>= 1)
        part += __shfl_down_sync(0xffffffffu, part, off);
    __shared__ float red[12];
    __shared__ float remf_sh;
    if ((tid & 31) == 0) red[tid >> 5] = part;
    __syncthreads();
    if (tid == 0) {
        float s = 0.f;
        #pragma unroll
        for (int i = 0; i < 12; ++i) s += red[i];
        const float y = sigf(s + bhalt[0]);
        float hpv = hp[row];
        hpv = hpv + y * (1.f - hpv);
        remf_sh = rem[row] + 1.f - hpv;
    }
    __syncthreads();
    const float rm = remf_sh * 0.1f;
    const float v0 = rm * hs0, v1 = rm * hs1;
    *(float2*)(x0 + o) = make_float2(v0, v1);
    __half a0, a1, b0, b1;
    split16(SCALE_ * v0, a0, b0);
    split16(SCALE_ * v1, a1, b1);
    __half* od = x02 + (size_t)row * KP_;
    const __half2 hh = __halves2half2(a0, a1);
    *(__half2*)(od + j2) = hh;
    *(__half2*)(od + H_ + j2) = hh;
    *(__half2*)(od + 2 * H_ + j2) = __halves2half2(b0, b1);
}

// ---------------- router + list building (fused); xb optional slot-1 addend -----
__global__ void router(const float* __restrict__ xa, const float* __restrict__ xb,
                       const float* __restrict__ Wg, const float* __restrict__ bg,
                       float* __restrict__ w, int* __restrict__ cnt,
                       int* __restrict__ rowid)
{
    const int row = blockIdx.x;
    const int tid = threadIdx.x;   // 128
    float p0 = 0.f, p1 = 0.f, p2 = 0.f, p3 = 0.f;
    for (int k = tid; k < H_; k += 128) {
        float xv = xa[(size_t)row * H_ + k];
        if (xb) xv += xb[(size_t)row * H_ + k];
        p0 += xv * Wg[k];
        p1 += xv * Wg[H_ + k];
        p2 += xv * Wg[2 * H_ + k];
        p3 += xv * Wg[3 * H_ + k];
    }
    __shared__ float red[4][128];
    red[0][tid] = p0; red[1][tid] = p1; red[2][tid] = p2; red[3][tid] = p3;
    __syncthreads();
    #pragma unroll
    for (int s = 64; s > 0; s >>= 1) {
        if (tid < s) {
            #pragma unroll
            for (int e = 0; e < 4; ++e) red[e][tid] += red[e][tid + s];
        }
        __syncthreads();
    }
    if (tid == 0) {
        float lg[4];
        #pragma unroll
        for (int e = 0; e < 4; ++e) lg[e] = red[e][0] + bg[e];
        int i1 = 0; float m1 = lg[0];
        #pragma unroll
        for (int e = 1; e < 4; ++e) if (lg[e] > m1) { m1 = lg[e]; i1 = e; }
        int i2 = -1; float m2 = -3.4e38f;
        #pragma unroll
        for (int e = 0; e < 4; ++e) if (e != i1 && lg[e] > m2) { m2 = lg[e]; i2 = e; }
        const float e2 = expf(m2 - m1);
        const float s  = 1.f + e2;
        float out4[4] = {0.f, 0.f, 0.f, 0.f};
        out4[i1] = 1.f / s;
        out4[i2] = e2 / s;
        #pragma unroll
        for (int e = 0; e < 4; ++e) w[row * 4 + e] = out4[e];
        const int s1 = atomicAdd(&cnt[i1], 1);
        rowid[(size_t)i1 * BP_ + s1] = row;                 // slot 0
        const int s2 = atomicAdd(&cnt[i2], 1);
        rowid[(size_t)i2 * BP_ + s2] = row | (1 << 30);     // slot 1
    }
}

__global__ void reset_cnt(int* cnt) {
    if (threadIdx.x < E_) cnt[threadIdx.x] = 0;
}
__global__ void pad_lists(const int* __restrict__ cnt, int* __restrict__ cntpad,
                          int* __restrict__ rowid)
{
    const int tid = threadIdx.x;   // 128
    for (int e = 0; e < E_; ++e) {
        const int n  = cnt[e];
        const int np = ((n + BM - 1) / BM) * BM;
        for (int i = n + tid; i < np; i += 128) rowid[(size_t)e * BP_ + i] = B_;
        if (tid == 0) cntpad[e] = np;
    }
}

// ---------------- final LayerNorm over slot-sum ----------------
__global__ void layernorm2(const float* __restrict__ s0, const float* __restrict__ s1,
                           const float* __restrict__ gamma, const float* __restrict__ beta,
                           float* __restrict__ out)
{
    const int row = blockIdx.x;
    const int tid = threadIdx.x;   // 256
    float v[D_ / 256];
    float s = 0.f;
    #pragma unroll
    for (int it = 0; it < D_ / 256; ++it) {
        const size_t idx = (size_t)row * D_ + tid + it * 256;
        v[it] = s0[idx] + s1[idx];
        s += v[it];
    }
    __shared__ float red[256];
    red[tid] = s;
    __syncthreads();
    #pragma unroll
    for (int st = 128; st > 0; st >>= 1) {
        if (tid < st) red[tid] += red[tid + st];
        __syncthreads();
    }
    const float mu = red[0] / (float)D_;
    __syncthreads();
    float s2 = 0.f;
    #pragma unroll
    for (int it = 0; it < D_ / 256; ++it) { const float d = v[it] - mu; s2 += d * d; }
    red[tid] = s2;
    __syncthreads();
    #pragma unroll
    for (int st = 128; st > 0; st >>= 1) {
        if (tid < st) red[tid] += red[tid + st];
        __syncthreads();
    }
    const float var = red[0] / (float)D_;
    const float inv = rsqrtf(var + 1e-5f);
    #pragma unroll
    for (int it = 0; it < D_ / 256; ++it) {
        const int cc = tid + it * 256;
        out[(size_t)row * D_ + cc] = (v[it] - mu) * inv * gamma[cc] + beta[cc];
    }
}

// ---------------- host ----------------
struct Ptrs {
    __half *act2, *hmid2, *Wi2, *Wh2, *W12, *W22, *W12b, *W22b;
    float *xWi, *gates, *c, *hsum, *x0, *acc1, *hp, *rem, *w;
    int *rowid, *cnt, *cntpad;
};

static Ptrs get_ptrs() {
    static Ptrs P = [] {
        Ptrs q{};
        cudaGetSymbolAddress((void**)&q.act2,   g_act2);
        cudaGetSymbolAddress((void**)&q.hmid2,  g_hmid2);
        cudaGetSymbolAddress((void**)&q.Wi2,    g_Wi2);
        cudaGetSymbolAddress((void**)&q.Wh2,    g_Wh2);
        cudaGetSymbolAddress((void**)&q.W12,    g_W12);
        cudaGetSymbolAddress((void**)&q.W22,    g_W22);
        cudaGetSymbolAddress((void**)&q.W12b,   g_W12b);
        cudaGetSymbolAddress((void**)&q.W22b,   g_W22b);
        cudaGetSymbolAddress((void**)&q.xWi,    g_xWi);
        cudaGetSymbolAddress((void**)&q.gates,  g_gates);
        cudaGetSymbolAddress((void**)&q.c,      g_c);
        cudaGetSymbolAddress((void**)&q.hsum,   g_hsum);
        cudaGetSymbolAddress((void**)&q.x0,     g_x0);
        cudaGetSymbolAddress((void**)&q.acc1,   g_acc1);
        cudaGetSymbolAddress((void**)&q.hp,     g_hp);
        cudaGetSymbolAddress((void**)&q.rem,    g_rem);
        cudaGetSymbolAddress((void**)&q.w,      g_w);
        cudaGetSymbolAddress((void**)&q.rowid,  g_rowid);
        cudaGetSymbolAddress((void**)&q.cnt,    g_cnt);
        cudaGetSymbolAddress((void**)&q.cntpad, g_cntpad);
        return q;
    }();
    return P;
}

extern "C" void kernel_launch(void* const* d_in, const int* in_sizes, int n_in,
                              void* d_out, int out_size)
{
    const float* x     = (const float*)d_in[0];
    const float* Wi    = (const float*)d_in[1];
    const float* Wh    = (const float*)d_in[2];
    const float* bi    = (const float*)d_in[3];
    const float* bh    = (const float*)d_in[4];
    const float* Whalt = (const float*)d_in[5];
    const float* bhalt = (const float*)d_in[6];
    const float* gateW = (const float*)d_in[7];
    const float* gateb = (const float*)d_in[8];
    const float* W1    = (const float*)d_in[9];
    const float* b1    = (const float*)d_in[10];
    const float* W2    = (const float*)d_in[11];
    const float* b2    = (const float*)d_in[12];
    const float* gamma = (const float*)d_in[13];
    const float* beta  = (const float*)d_in[14];
    float* out = (float*)d_out;

    Ptrs P = get_ptrs();

    cudaFuncSetAttribute((const void*)tgemm<0>, cudaFuncAttributeMaxDynamicSharedMemorySize, SMEM_DYN);
    cudaFuncSetAttribute((const void*)tgemm<1>, cudaFuncAttributeMaxDynamicSharedMemorySize, SMEM_DYN);
    cudaFuncSetAttribute((const void*)tgemm<2>, cudaFuncAttributeMaxDynamicSharedMemorySize, SMEM_DYN);
    cudaFuncSetAttribute((const void*)tgemm<3>, cudaFuncAttributeMaxDynamicSharedMemorySize, SMEM_DYN);
    cudaFuncSetAttribute((const void*)tgemm<5>, cudaFuncAttributeMaxDynamicSharedMemorySize, SMEM_DYN);

    const size_t lvl2off = (size_t)E_ * H_ * H_;

    // conversions
    convW3v<<<G4_, 192>>>(Wi, P.Wi2);
    convW3v<<<G4_, 192>>>(Wh, P.Wh2);
    convW3v<<<E_ * H_, 192>>>(W1, P.W12);
    convW3v<<<E_ * D_, 192>>>(W2, P.W22);
    convW2v<<<E_ * H_, 192>>>(W1 + lvl2off, P.W12b);
    convW2v<<<E_ * D_, 192>>>(W2 + lvl2off, P.W22b);
    convA3v<<<B_, 192>>>(x, P.act2);

    // zero recurrent state
    fill0<<<2048, 256>>>(P.c,    (size_t)B_ * H_);
    fill0<<<2048, 256>>>(P.hsum, (size_t)B_ * H_);
    fill0<<<64,   256>>>(P.hp,   (size_t)B_);
    fill0<<<64,   256>>>(P.rem,  (size_t)B_);

    // xWi = x @ Wi^T + bi + bh
    dim3 gridG(G4_ / BN, B_ / BM, 1);
    tgemm<0><<<gridG, 256, SMEM_DYN>>>(P.act2, P.Wi2, P.xWi, G4_, KP_,
                                       bi, bh, nullptr, nullptr, nullptr,
                                       nullptr, nullptr, 0, 0, 0, 0);

    // steps 0..8 (t=0 uses gates == xWi)
    for (int t = 0; t < T_ - 1; ++t) {
        const float* gptr;
        if (t == 0) {
            gptr = P.xWi;
        } else {
            tgemm<1><<<gridG, 256, SMEM_DYN>>>(P.act2, P.Wh2, P.gates, G4_, KP_,
                                               bi, nullptr, P.xWi, nullptr, nullptr,
                                               nullptr, nullptr, 0, 0, 0, 0);
            gptr = P.gates;
        }
        lstm_cell<<<B_, 384>>>(gptr, Whalt, bhalt, P.c, P.act2, P.hsum, P.hp, P.rem);
    }
    // step 9: GEMM + fused cell+avg (writes x0 and act2 avg-triple)
    tgemm<1><<<gridG, 256, SMEM_DYN>>>(P.act2, P.Wh2, P.gates, G4_, KP_,
                                       bi, nullptr, P.xWi, nullptr, nullptr,
                                       nullptr, nullptr, 0, 0, 0, 0);
    lstm_cell_last<<<B_, 384>>>(P.gates, Whalt, bhalt, P.c, P.hsum, P.hp, P.rem,
                                P.x0, P.act2);

    // ---- level 1 (split-3) ----
    dim3 gridE(H_ / BN, BP_ / BM, E_);
    reset_cnt<<<1, 32>>>(P.cnt);
    router<<<B_, 128>>>(P.x0, nullptr, gateW, gateb, P.w, P.cnt, P.rowid);
    pad_lists<<<1, 128>>>(P.cnt, P.cntpad, P.rowid);
    tgemm<2><<<gridE, 256, SMEM_DYN>>>(P.act2, P.W12, nullptr, H_, KP_,
                                       b1, nullptr, nullptr, nullptr, P.hmid2,
                                       P.cntpad, P.rowid,
                                       0, (size_t)H_ * KP_, H_, (size_t)BP_ * KP_);
    tgemm<3><<<gridE, 256, SMEM_DYN>>>(P.hmid2, P.W22, P.acc1, D_, KP_,
                                       b2, nullptr, nullptr, P.w, nullptr,
                                       P.cntpad, P.rowid,
                                       (size_t)BP_ * KP_, (size_t)D_ * KP_, D_, 0);

    // ---- level 2 (split-2) ----
    convA2v2<<<B_, 192>>>(P.acc1, P.acc1 + (size_t)BP_ * D_, P.act2);
    reset_cnt<<<1, 32>>>(P.cnt);
    router<<<B_, 128>>>(P.acc1, P.acc1 + (size_t)BP_ * D_,
                        gateW + (size_t)E_ * H_, gateb + E_, P.w, P.cnt, P.rowid);
    pad_lists<<<1, 128>>>(P.cnt, P.cntpad, P.rowid);
    tgemm<5><<<gridE, 256, SMEM_DYN>>>(P.act2, P.W12b, nullptr, H_, KP2_,
                                       b1 + (size_t)E_ * H_, nullptr, nullptr, nullptr, P.hmid2,
                                       P.cntpad, P.rowid,
                                       0, (size_t)H_ * KP2_, H_, (size_t)BP_ * KP2_);
    tgemm<3><<<gridE, 256, SMEM_DYN>>>(P.hmid2, P.W22b, P.xWi, D_, KP2_,
                                       b2 + (size_t)E_ * D_, nullptr, nullptr, P.w, nullptr,
                                       P.cntpad, P.rowid,
                                       (size_t)BP_ * KP2_, (size_t)D_ * KP2_, D_, 0);

    layernorm2<<<B_, 256>>>(P.xWi, P.xWi + (size_t)BP_ * D_, gamma, beta, out);
}